// round 14
// baseline (speedup 1.0000x reference)
#include <cuda_runtime.h>
#include <cuda_fp16.h>
#include <math.h>
#include <stdint.h>

#define B 8
#define N 1024
#define H 16
#define D 64
#define HD 1024

// Scratch (allocation-free)
__device__ __half g_hsH[B * N * HD];       // fp16 copy of hidden_states
__device__ __half g_wH[3 * HD * HD];       // fp16 copy of qkv_w
__device__ __half g_Qh[B * H * N * D];     // original token order, *0.125*log2e
__device__ __half g_Kh[B * H * N * D];     // keys compacted (unmasked first)
__device__ __half g_Vh[B * H * N * D];     // [np][d] row-major, compacted
__device__ float  g_RB[H * N * N];         // (rel+rel2)*log2e, ORIGINAL key order
__device__ float  g_Crow[H * N];           // per (h,q) softmax cap (log2 units)
__device__ int    g_invp[B * N];           // permuted pos -> orig key
__device__ int    g_nun[B];                // # unmasked keys
__device__ float  g_msum[B * HD];          // sum of hs over masked tokens
__device__ float  g_Vsum[B * HD];          // sum of V over masked keys (fp32)

#define LOG2E 1.44269504f

__device__ __forceinline__ uint32_t f2h2(float lo, float hi) {
    __half2 h = __floats2half2_rn(lo, hi);
    return *(uint32_t*)&h;
}

__device__ __forceinline__ uint32_t ex2h2(uint32_t x) {
    uint32_t d;
    asm("ex2.approx.f16x2 %0, %1;" : "=r"(d) : "r"(x));
    return d;
}

__device__ __forceinline__ void mma16(float* d, const uint32_t* a, const uint32_t* b) {
    asm volatile(
        "mma.sync.aligned.m16n8k16.row.col.f32.f16.f16.f32 "
        "{%0,%1,%2,%3}, {%4,%5,%6,%7}, {%8,%9}, {%0,%1,%2,%3};"
        : "+f"(d[0]), "+f"(d[1]), "+f"(d[2]), "+f"(d[3])
        : "r"(a[0]), "r"(a[1]), "r"(a[2]), "r"(a[3]), "r"(b[0]), "r"(b[1]));
}

__device__ __forceinline__ void ldm4(uint32_t* d, uint32_t a) {
    asm volatile("ldmatrix.sync.aligned.m8n8.x4.shared.b16 {%0,%1,%2,%3}, [%4];"
        : "=r"(d[0]), "=r"(d[1]), "=r"(d[2]), "=r"(d[3]) : "r"(a));
}

__device__ __forceinline__ void ldm2t(uint32_t* d, uint32_t a) {
    asm volatile("ldmatrix.sync.aligned.m8n8.x2.trans.shared.b16 {%0,%1}, [%2];"
        : "=r"(d[0]), "=r"(d[1]) : "r"(a));
}

#define STS128V(addr, u) asm volatile("st.shared.v4.b32 [%0], {%1,%2,%3,%4};" \
    :: "r"(addr), "r"((u).x), "r"((u).y), "r"((u).z), "r"((u).w) : "memory")
#define CP_ASYNC16(dst, src) asm volatile( \
    "cp.async.cg.shared.global [%0], [%1], 16;" :: "r"(dst), "l"(src) : "memory")
#define CP_COMMIT() asm volatile("cp.async.commit_group;" ::: "memory")
#define CP_WAIT0()  asm volatile("cp.async.wait_group 0;" ::: "memory")
#define CP_WAIT1()  asm volatile("cp.async.wait_group 1;" ::: "memory")

__device__ __forceinline__ uint32_t smem_u32(const void* p) {
    uint32_t a;
    asm("{ .reg .u64 t; cvta.to.shared.u64 t, %1; cvt.u32.u64 %0, t; }"
        : "=r"(a) : "l"(p));
    return a;
}

// ---------------------------------------------------------------------------
// Kernel 0: combined bias = (rel_pos + rel_2d_pos) * log2e
// ---------------------------------------------------------------------------
__global__ __launch_bounds__(256) void bias_kernel(
    const float* __restrict__ rel, const float* __restrict__ rel2)
{
    size_t i = ((size_t)blockIdx.x * 256 + threadIdx.x) * 4;
    float4 a = *(const float4*)&rel[i];
    float4 b = *(const float4*)&rel2[i];
    a.x = (a.x + b.x) * LOG2E; a.y = (a.y + b.y) * LOG2E;
    a.z = (a.z + b.z) * LOG2E; a.w = (a.w + b.w) * LOG2E;
    *(float4*)&g_RB[i] = a;
}

// ---------------------------------------------------------------------------
// Kernel R: per-row softmax cap C[h,q] = max_k RB[h,q,k] + 4*log2e
// ---------------------------------------------------------------------------
__global__ __launch_bounds__(256) void rbmax_kernel()
{
    const int row = blockIdx.x * 8 + (threadIdx.x >> 5);
    const int lane = threadIdx.x & 31;
    const float* r = g_RB + (size_t)row * N;
    float m = -1e30f;
#pragma unroll
    for (int i = 0; i < 8; i++) {
        float4 v = ((const float4*)r)[lane + 32 * i];
        m = fmaxf(m, fmaxf(fmaxf(v.x, v.y), fmaxf(v.z, v.w)));
    }
#pragma unroll
    for (int off = 16; off > 0; off >>= 1)
        m = fmaxf(m, __shfl_xor_sync(0xffffffffu, m, off));
    if (lane == 0) g_Crow[row] = m + 4.0f * LOG2E;
}

// ---------------------------------------------------------------------------
// Kernels C: fp32 -> fp16 bulk conversion into DEVICE globals
// ---------------------------------------------------------------------------
__global__ __launch_bounds__(256) void cvt_hs_kernel(const float* __restrict__ src)
{
    size_t i = ((size_t)blockIdx.x * 256 + threadIdx.x) * 8;
    float4 a = *(const float4*)&src[i];
    float4 b = *(const float4*)&src[i + 4];
    uint4 u;
    u.x = f2h2(a.x, a.y); u.y = f2h2(a.z, a.w);
    u.z = f2h2(b.x, b.y); u.w = f2h2(b.z, b.w);
    *(uint4*)&g_hsH[i] = u;
}

__global__ __launch_bounds__(256) void cvt_w_kernel(const float* __restrict__ src)
{
    size_t i = ((size_t)blockIdx.x * 256 + threadIdx.x) * 8;
    float4 a = *(const float4*)&src[i];
    float4 b = *(const float4*)&src[i + 4];
    uint4 u;
    u.x = f2h2(a.x, a.y); u.y = f2h2(a.z, a.w);
    u.z = f2h2(b.x, b.y); u.w = f2h2(b.z, b.w);
    *(uint4*)&g_wH[i] = u;
}

// ---------------------------------------------------------------------------
// Kernel P: stable partition of keys per batch (unmasked first).
// ---------------------------------------------------------------------------
__global__ __launch_bounds__(1024) void perm_kernel(const int* __restrict__ mask)
{
    const int b = blockIdx.x, k = threadIdx.x;
    const int lane = k & 31, wid = k >> 5;
    const int u = (mask[b * N + k] == 0) ? 1 : 0;
    unsigned bal = __ballot_sync(0xffffffffu, u);
    int eU = __popc(bal & ((1u << lane) - 1));

    __shared__ int wsum[32];
    if (lane == 31) wsum[wid] = eU + u;
    __syncthreads();
    if (wid == 0) {
        int v = wsum[lane];
#pragma unroll
        for (int off = 1; off < 32; off <<= 1) {
            int t = __shfl_up_sync(0xffffffffu, v, off);
            if (lane >= off) v += t;
        }
        wsum[lane] = v;
    }
    __syncthreads();
    const int warp_off = (wid > 0) ? wsum[wid - 1] : 0;
    const int nun = wsum[31];
    const int scanU = warp_off + eU;
    const int pos = u ? scanU : (nun + (k - scanU));
    g_invp[b * N + pos] = k;
    if (k == 0) g_nun[b] = nun;
}

// ---------------------------------------------------------------------------
// Kernel M: msum[b][k] = sum over MASKED tokens of hs[b][n][k]
// ---------------------------------------------------------------------------
__global__ __launch_bounds__(128) void msum_kernel(
    const float* __restrict__ hs, const int* __restrict__ mask)
{
    __shared__ int mk_s[N];
    const int b = blockIdx.y;
    const int k = blockIdx.x * 128 + threadIdx.x;
    for (int i = threadIdx.x; i < N; i += 128) mk_s[i] = mask[b * N + i];
    __syncthreads();
    float s = 0.0f;
    for (int n = 0; n < N; n++)
        if (mk_s[n]) s += hs[((size_t)b * N + n) * HD + k];
    g_msum[b * HD + k] = s;
}

// ---------------------------------------------------------------------------
// Kernel G: Vsum[b][o] = msum[b] . Wv[o] + nmask * vb[o]
// ---------------------------------------------------------------------------
__global__ __launch_bounds__(256) void vgemm_kernel(
    const float* __restrict__ w, const float* __restrict__ vb)
{
    const int lane = threadIdx.x & 31;
    const int idx = blockIdx.x * 8 + (threadIdx.x >> 5);
    const int b = idx >> 10, o = idx & 1023;
    const float* wr = w + (size_t)(2048 + o) * HD;
    const float* ms = g_msum + b * HD;
    float s = 0.0f;
#pragma unroll
    for (int it = 0; it < 8; it++) {
        int k4 = it * 32 + lane;
        float4 wv = ((const float4*)wr)[k4];
        float4 mv = ((const float4*)ms)[k4];
        s += wv.x * mv.x + wv.y * mv.y + wv.z * mv.z + wv.w * mv.w;
    }
#pragma unroll
    for (int off = 16; off > 0; off >>= 1)
        s += __shfl_xor_sync(0xffffffffu, s, off);
    if (lane == 0) {
        float nm = (float)(N - g_nun[b]);
        g_Vsum[b * HD + o] = s + nm * vb[o];
    }
}

// ---------------------------------------------------------------------------
// Kernel 1: QKV projection, fp16 inputs, cp.async 3-stage pipeline, BK=32,
// ldmatrix fragment loads. 512 threads, tile 128(o) x 256(tok).
// ---------------------------------------------------------------------------
#define QP 20
#define QA_W (128 * QP)
#define QB_W (256 * QP)
#define QS_W (QA_W + QB_W)
#define QKV_DYN_BYTES (3 * QS_W * 4)

__global__ __launch_bounds__(512) void qkv_kernel(
    const float* __restrict__ qb, const float* __restrict__ vb)
{
    extern __shared__ uint32_t sm[];
    __shared__ int invp_s[256];
    const uint32_t smA = smem_u32(sm);

    const int tid  = threadIdx.x;
    const int lane = tid & 31;
    const int warp = tid >> 5;
    const int wo = (warp >> 2) * 32;
    const int wt = (warp & 3) * 64;
    const int o0 = blockIdx.x * 128;
    const int t0 = blockIdx.y * 256;
    const int r = lane >> 2;
    const int c = lane & 3;
    const int b0 = t0 >> 10;
    const int t0l = t0 & 1023;
    const int seg = o0 >> 10;
    const int am = ((lane >> 3) & 1) * 8 + (lane & 7);
    const int ac = (lane >> 4) * 4;

    if (seg != 0) {
        const int ntt = (g_nun[b0] + 255) >> 8;
        if ((t0l >> 8) >= ntt) return;
    }

    if (tid < 256) invp_s[tid] = g_invp[b0 * N + t0l + tid];
    __syncthreads();

    float acc[2][8][4];
#pragma unroll
    for (int g = 0; g < 2; g++)
#pragma unroll
        for (int nj = 0; nj < 8; nj++)
#pragma unroll
            for (int q = 0; q < 4; q++) acc[g][nj][q] = 0.0f;

    auto load_stage = [&](int kc, int buf) {
        const int k0 = kc * 32;
        const uint32_t base = smA + buf * QS_W * 4;
        {
            int row = tid >> 2, f = tid & 3;
            CP_ASYNC16(base + (row * QP + 4 * f) * 4,
                       g_wH + (size_t)(o0 + row) * HD + k0 + 8 * f);
        }
#pragma unroll
        for (int i = 0; i < 2; i++) {
            int slot = tid + 512 * i;
            int row = slot >> 2, f = slot & 3;
            int grow = seg ? (b0 * N + invp_s[row]) : (t0 + row);
            CP_ASYNC16(base + (QA_W + row * QP + 4 * f) * 4,
                       g_hsH + (size_t)grow * HD + k0 + 8 * f);
        }
    };

    load_stage(0, 0); CP_COMMIT();
    load_stage(1, 1); CP_COMMIT();

    for (int kc = 0; kc < 32; kc++) {
        const int buf = kc - (kc / 3) * 3;
        CP_WAIT1();
        __syncthreads();

        if (kc + 2 < 32) load_stage(kc + 2, (kc + 2) - ((kc + 2) / 3) * 3);
        CP_COMMIT();

        const uint32_t Aa = smA + (buf * QS_W) * 4;
        const uint32_t Ba = Aa + QA_W * 4;
#pragma unroll
        for (int ks = 0; ks < 2; ks++) {
            const int kb = ks * 8;
            uint32_t a[2][4], bb[8][2];
#pragma unroll
            for (int g = 0; g < 2; g++)
                ldm4(a[g], Aa + ((wo + 16 * g + am) * QP + kb + ac) * 4);
#pragma unroll
            for (int j = 0; j < 4; j++) {
                uint32_t t4[4];
                ldm4(t4, Ba + ((wt + 16 * j + am) * QP + kb + ac) * 4);
                bb[2 * j][0] = t4[0];     bb[2 * j][1] = t4[2];
                bb[2 * j + 1][0] = t4[1]; bb[2 * j + 1][1] = t4[3];
            }
#pragma unroll
            for (int g = 0; g < 2; g++)
#pragma unroll
                for (int nj = 0; nj < 8; nj++)
                    mma16(acc[g][nj], a[g], bb[nj]);
        }
    }

    // epilogue: Q scaled by 0.125*log2e (log2-domain softmax)
    const float QSC = 0.125f * LOG2E;
#pragma unroll
    for (int g = 0; g < 2; g++) {
#pragma unroll
        for (int rr = 0; rr < 2; rr++) {
            int o = o0 + wo + 16 * g + r + 8 * rr;
            int hd = o & 1023, h = hd >> 6, d = hd & 63;
            float addb = (seg == 0) ? qb[hd] : ((seg == 2) ? vb[hd] : 0.0f);
#pragma unroll
            for (int nj = 0; nj < 8; nj++) {
                int tokl = wt + 8 * nj + 2 * c;
                int n = t0l + tokl;
                float v0 = acc[g][nj][2 * rr + 0];
                float v1 = acc[g][nj][2 * rr + 1];
                size_t idx = (((size_t)(b0 * H + h)) * N + n) * D + d;
                if (seg == 0) {
                    g_Qh[idx]     = __float2half((v0 + addb) * QSC);
                    g_Qh[idx + D] = __float2half((v1 + addb) * QSC);
                } else if (seg == 1) {
                    g_Kh[idx]     = __float2half(v0);
                    g_Kh[idx + D] = __float2half(v1);
                } else {
                    g_Vh[idx]     = __float2half(v0 + addb);
                    g_Vh[idx + D] = __float2half(v1 + addb);
                }
            }
        }
    }
}

// ---------------------------------------------------------------------------
// Kernel 2: flash attention, fixed per-row cap softmax (no running max),
// ex2.f16x2 exp, row sums via ones-MMA. P in registers. 2 CTAs/SM.
// ---------------------------------------------------------------------------
#define AT_PITCH 36
#define AT_KW (64 * AT_PITCH)
#define AT_DYN_BYTES ((4 * AT_KW + N) * 4)

__global__ __launch_bounds__(256, 2) void attn_kernel(float* __restrict__ out)
{
    extern __shared__ uint32_t dynsm[];
    int* invp_s = (int*)(dynsm + 4 * AT_KW);
    const uint32_t dynA = smem_u32(dynsm);

    const int tid  = threadIdx.x;
    const int lane = tid & 31;
    const int warp = tid >> 5;
    const int q0 = blockIdx.x * 128;
    const int h  = blockIdx.y;
    const int b  = blockIdx.z;
    const int qw = warp * 16;
    const int r = lane >> 2;
    const int c = lane & 3;
    const int am = ((lane >> 3) & 1) * 8 + (lane & 7);
    const int ac = (lane >> 4) * 4;

    const __half* Qh = g_Qh + (size_t)(b * H + h) * N * D;
    const __half* Kh = g_Kh + (size_t)(b * H + h) * N * D;
    const __half* Vh = g_Vh + (size_t)(b * H + h) * N * D;
    const float*  rb = g_RB + (size_t)h * N * N;

    const int nun = g_nun[b];
    const int ntiles = (nun + 63) >> 6;
    const int row0 = q0 + qw + r;
    const float C0 = g_Crow[h * N + row0];
    const float C1 = g_Crow[h * N + row0 + 8];

    for (int i = tid; i < N; i += 256) invp_s[i] = g_invp[b * N + i];

    // stage Q tile (128 x 64) through the K-tile smem, lift fragments
#pragma unroll
    for (int i = 0; i < 4; i++) {
        int slot = tid + 256 * i;
        int row = slot >> 3, j = slot & 7;
        uint4 v = ((const uint4*)(Qh + (size_t)(q0 + row) * D))[j];
        STS128V(dynA + (row * AT_PITCH + 4 * j) * 4, v);
    }
    __syncthreads();

    uint32_t qa[4][4];
#pragma unroll
    for (int ks = 0; ks < 4; ks++)
        ldm4(qa[ks], dynA + ((qw + am) * AT_PITCH + 8 * ks + ac) * 4);
    __syncthreads();

    auto load_tile = [&](int t, int buf) {
        const int k0 = t * 64;
        const uint32_t kb = dynA + (buf * AT_KW) * 4;
        const uint32_t vbuf = dynA + ((2 + buf) * AT_KW) * 4;
#pragma unroll
        for (int i = 0; i < 2; i++) {
            int slot = tid + 256 * i;
            int row = slot >> 3, j = slot & 7;
            CP_ASYNC16(kb + (row * AT_PITCH + 4 * j) * 4,
                       Kh + (size_t)(k0 + row) * D + 8 * j);
            CP_ASYNC16(vbuf + (row * AT_PITCH + 4 * j) * 4,
                       Vh + (size_t)(k0 + row) * D + 8 * j);
        }
    };

    float oacc[8][4];
#pragma unroll
    for (int nb = 0; nb < 8; nb++)
#pragma unroll
        for (int q = 0; q < 4; q++) oacc[nb][q] = 0.0f;
    float lacc[4] = {0.0f, 0.0f, 0.0f, 0.0f};
    const uint32_t ones[2] = {0x3C003C00u, 0x3C003C00u};   // half2(1,1)

    load_tile(0, 0);
    CP_COMMIT();

    for (int t = 0; t < ntiles; t++) {
        const int buf = t & 1;
        const int k0 = t * 64;
        CP_WAIT0();
        __syncthreads();

        if (t + 1 < ntiles) {
            load_tile(t + 1, buf ^ 1);
            CP_COMMIT();
        }

        const uint32_t KsA = dynA + (buf * AT_KW) * 4;
        const uint32_t vldm = dynA + ((2 + buf) * AT_KW + (lane & 15) * AT_PITCH) * 4;

        // S = Q @ K^T (log2-scaled by construction)
        float sacc[8][4];
#pragma unroll
        for (int nb = 0; nb < 8; nb++)
#pragma unroll
            for (int q = 0; q < 4; q++) sacc[nb][q] = 0.0f;

#pragma unroll
        for (int ks = 0; ks < 4; ks++) {
#pragma unroll
            for (int j = 0; j < 4; j++) {
                uint32_t t4[4];
                ldm4(t4, KsA + ((16 * j + am) * AT_PITCH + 8 * ks + ac) * 4);
                uint32_t b0[2] = {t4[0], t4[2]};
                uint32_t b1[2] = {t4[1], t4[3]};
                mma16(sacc[2 * j],     qa[ks], b0);
                mma16(sacc[2 * j + 1], qa[ks], b1);
            }
        }

        // bias + tail cut + fixed-cap exp2 (fp16x2 MUFU), P straight to A-frags
        uint32_t ph[8][2];
#pragma unroll
        for (int nb = 0; nb < 8; nb++) {
            int p0 = k0 + 8 * nb + 2 * c;
            int c0 = invp_s[p0], c1 = invp_s[p0 + 1];
            float s0 = sacc[nb][0] + rb[(size_t)row0 * N + c0] - C0;
            float s1 = sacc[nb][1] + rb[(size_t)row0 * N + c1] - C0;
            float s2 = sacc[nb][2] + rb[(size_t)(row0 + 8) * N + c0] - C1;
            float s3 = sacc[nb][3] + rb[(size_t)(row0 + 8) * N + c1] - C1;
            if (p0 >= nun)     { s0 = -1e30f; s2 = -1e30f; }
            if (p0 + 1 >= nun) { s1 = -1e30f; s3 = -1e30f; }
            ph[nb][0] = ex2h2(f2h2(s0, s1));
            ph[nb][1] = ex2h2(f2h2(s2, s3));
        }

        // O += P @ V, and l += P @ ones (row sums on the tensor pipe)
#pragma unroll
        for (int ks = 0; ks < 4; ks++) {
            uint32_t pa[4];
            pa[0] = ph[2 * ks][0];
            pa[1] = ph[2 * ks][1];
            pa[2] = ph[2 * ks + 1][0];
            pa[3] = ph[2 * ks + 1][1];
            mma16(lacc, pa, ones);
            const uint32_t vbase = vldm + (16 * ks * AT_PITCH) * 4;
#pragma unroll
            for (int nb = 0; nb < 8; nb++) {
                uint32_t bbv[2];
                ldm2t(bbv, vbase + nb * 16);
                mma16(oacc[nb], pa, bbv);
            }
        }
    }

    // analytic masked-key correction (masked scores are const 1e-8)
    const int nmask = N - nun;
    const float pm0 = exp2f(1e-8f * LOG2E - C0);
    const float pm1 = exp2f(1e-8f * LOG2E - C1);
    const float l0 = lacc[0] + (float)nmask * pm0;
    const float l1 = lacc[2] + (float)nmask * pm1;

    const float* vs = g_Vsum + b * HD + h * D;
    const float inv0 = 1.0f / l0, inv1 = 1.0f / l1;
#pragma unroll
    for (int nb = 0; nb < 8; nb++) {
        int d = 8 * nb + 2 * c;
        float2 vv = *(const float2*)&vs[d];
        float2 v0; v0.x = (oacc[nb][0] + pm0 * vv.x) * inv0;
        v0.y = (oacc[nb][1] + pm0 * vv.y) * inv0;
        *(float2*)&out[((size_t)b * N + row0) * HD + h * D + d] = v0;
        float2 v1; v1.x = (oacc[nb][2] + pm1 * vv.x) * inv1;
        v1.y = (oacc[nb][3] + pm1 * vv.y) * inv1;
        *(float2*)&out[((size_t)b * N + row0 + 8) * HD + h * D + d] = v1;
    }
}

extern "C" void kernel_launch(void* const* d_in, const int* in_sizes, int n_in,
                              void* d_out, int out_size)
{
    (void)in_sizes; (void)n_in; (void)out_size;
    const float* hs   = (const float*)d_in[0];
    const float* w    = (const float*)d_in[1];
    const float* qb   = (const float*)d_in[2];
    const float* vb   = (const float*)d_in[3];
    const float* rel  = (const float*)d_in[4];
    const float* rel2 = (const float*)d_in[5];
    const int*   mask = (const int*)d_in[6];
    float* out = (float*)d_out;

    cudaFuncSetAttribute(qkv_kernel,
                         cudaFuncAttributeMaxDynamicSharedMemorySize, QKV_DYN_BYTES);
    cudaFuncSetAttribute(attn_kernel,
                         cudaFuncAttributeMaxDynamicSharedMemorySize, AT_DYN_BYTES);

    cvt_hs_kernel<<<(B * N * HD) / (256 * 8), 256>>>(hs);
    cvt_w_kernel<<<(3 * HD * HD) / (256 * 8), 256>>>(w);
    bias_kernel<<<(H * N * N) / (256 * 4), 256>>>(rel, rel2);
    rbmax_kernel<<<(H * N) / 8, 256>>>();
    perm_kernel<<<B, 1024>>>(mask);
    msum_kernel<<<dim3(8, B), 128>>>(hs, mask);

    dim3 g1(3 * HD / 128, (B * N) / 256);        // (24, 32)
    qkv_kernel<<<g1, 512, QKV_DYN_BYTES>>>(qb, vb);

    vgemm_kernel<<<1024, 256>>>(w, vb);

    dim3 g2(N / 128, H, B);                      // (8, 16, 8)
    attn_kernel<<<g2, 256, AT_DYN_BYTES>>>(out);
}

// round 15
// speedup vs baseline: 1.0861x; 1.0861x over previous
#include <cuda_runtime.h>
#include <cuda_fp16.h>
#include <math.h>
#include <stdint.h>

#define B 8
#define N 1024
#define H 16
#define D 64
#define HD 1024

// Scratch (allocation-free)
__device__ __half g_hsH[B * N * HD];       // fp16 copy of hidden_states
__device__ __half g_wH[3 * HD * HD];       // fp16 copy of qkv_w
__device__ __half g_Qh[B * H * N * D];     // original token order, *0.125
__device__ __half g_Kh[B * H * N * D];     // keys compacted (unmasked first)
__device__ __half g_Vh[B * H * N * D];     // [np][d] row-major, compacted
__device__ float  g_RBp[H * N * N];        // bias TRANSPOSED+PAIRED: [h][k][qp]
                                           // qp = 16*(q>>4) + 2*(q&7) + ((q>>3)&1)
__device__ int    g_invp[B * N];           // permuted pos -> orig key
__device__ int    g_nun[B];                // # unmasked keys
__device__ float  g_msum[B * HD];          // sum of hs over masked tokens
__device__ float  g_Vsum[B * HD];          // sum of V over masked keys (fp32)

__device__ __forceinline__ uint32_t f2h2(float lo, float hi) {
    __half2 h = __floats2half2_rn(lo, hi);
    return *(uint32_t*)&h;
}

__device__ __forceinline__ void mma16(float* d, const uint32_t* a, const uint32_t* b) {
    asm volatile(
        "mma.sync.aligned.m16n8k16.row.col.f32.f16.f16.f32 "
        "{%0,%1,%2,%3}, {%4,%5,%6,%7}, {%8,%9}, {%0,%1,%2,%3};"
        : "+f"(d[0]), "+f"(d[1]), "+f"(d[2]), "+f"(d[3])
        : "r"(a[0]), "r"(a[1]), "r"(a[2]), "r"(a[3]), "r"(b[0]), "r"(b[1]));
}

__device__ __forceinline__ void ldm4(uint32_t* d, uint32_t a) {
    asm volatile("ldmatrix.sync.aligned.m8n8.x4.shared.b16 {%0,%1,%2,%3}, [%4];"
        : "=r"(d[0]), "=r"(d[1]), "=r"(d[2]), "=r"(d[3]) : "r"(a));
}

__device__ __forceinline__ void ldm2t(uint32_t* d, uint32_t a) {
    asm volatile("ldmatrix.sync.aligned.m8n8.x2.trans.shared.b16 {%0,%1}, [%2];"
        : "=r"(d[0]), "=r"(d[1]) : "r"(a));
}

#define STS128V(addr, u) asm volatile("st.shared.v4.b32 [%0], {%1,%2,%3,%4};" \
    :: "r"(addr), "r"((u).x), "r"((u).y), "r"((u).z), "r"((u).w) : "memory")
#define CP_ASYNC16(dst, src) asm volatile( \
    "cp.async.cg.shared.global [%0], [%1], 16;" :: "r"(dst), "l"(src) : "memory")
#define CP_COMMIT() asm volatile("cp.async.commit_group;" ::: "memory")
#define CP_WAIT0()  asm volatile("cp.async.wait_group 0;" ::: "memory")
#define CP_WAIT1()  asm volatile("cp.async.wait_group 1;" ::: "memory")

__device__ __forceinline__ uint32_t smem_u32(const void* p) {
    uint32_t a;
    asm("{ .reg .u64 t; cvta.to.shared.u64 t, %1; cvt.u32.u64 %0, t; }"
        : "=r"(a) : "l"(p));
    return a;
}

// ---------------------------------------------------------------------------
// Kernel 0: biasT = transpose(rel + rel_2d) into paired layout [h][k][qp].
// 64x64 smem tile transpose; reads and writes coalesced.
// ---------------------------------------------------------------------------
__global__ __launch_bounds__(256) void biasT_kernel(
    const float* __restrict__ rel, const float* __restrict__ rel2)
{
    __shared__ float ts[64][65];
    const int h  = blockIdx.z;
    const int qb = blockIdx.y * 64;
    const int kb = blockIdx.x * 64;

#pragma unroll
    for (int i = 0; i < 16; i++) {
        int idx = threadIdx.x + 256 * i;
        int ql = idx >> 6, kl = idx & 63;
        size_t src = ((size_t)h * N + qb + ql) * N + kb + kl;
        ts[ql][kl] = rel[src] + rel2[src];
    }
    __syncthreads();

#pragma unroll
    for (int i = 0; i < 16; i++) {
        int idx = threadIdx.x + 256 * i;
        int kl = idx >> 6, ql = idx & 63;
        int pos = ((ql >> 4) << 4) + ((ql & 7) << 1) + ((ql >> 3) & 1);
        g_RBp[((size_t)h * N + kb + kl) * N + qb + pos] = ts[ql][kl];
    }
}

// ---------------------------------------------------------------------------
// Kernels C: fp32 -> fp16 bulk conversion into DEVICE globals
// ---------------------------------------------------------------------------
__global__ __launch_bounds__(256) void cvt_hs_kernel(const float* __restrict__ src)
{
    size_t i = ((size_t)blockIdx.x * 256 + threadIdx.x) * 8;
    float4 a = *(const float4*)&src[i];
    float4 b = *(const float4*)&src[i + 4];
    uint4 u;
    u.x = f2h2(a.x, a.y); u.y = f2h2(a.z, a.w);
    u.z = f2h2(b.x, b.y); u.w = f2h2(b.z, b.w);
    *(uint4*)&g_hsH[i] = u;
}

__global__ __launch_bounds__(256) void cvt_w_kernel(const float* __restrict__ src)
{
    size_t i = ((size_t)blockIdx.x * 256 + threadIdx.x) * 8;
    float4 a = *(const float4*)&src[i];
    float4 b = *(const float4*)&src[i + 4];
    uint4 u;
    u.x = f2h2(a.x, a.y); u.y = f2h2(a.z, a.w);
    u.z = f2h2(b.x, b.y); u.w = f2h2(b.z, b.w);
    *(uint4*)&g_wH[i] = u;
}

// ---------------------------------------------------------------------------
// Kernel P: stable partition of keys per batch (unmasked first).
// ---------------------------------------------------------------------------
__global__ __launch_bounds__(1024) void perm_kernel(const int* __restrict__ mask)
{
    const int b = blockIdx.x, k = threadIdx.x;
    const int lane = k & 31, wid = k >> 5;
    const int u = (mask[b * N + k] == 0) ? 1 : 0;
    unsigned bal = __ballot_sync(0xffffffffu, u);
    int eU = __popc(bal & ((1u << lane) - 1));

    __shared__ int wsum[32];
    if (lane == 31) wsum[wid] = eU + u;
    __syncthreads();
    if (wid == 0) {
        int v = wsum[lane];
#pragma unroll
        for (int off = 1; off < 32; off <<= 1) {
            int t = __shfl_up_sync(0xffffffffu, v, off);
            if (lane >= off) v += t;
        }
        wsum[lane] = v;
    }
    __syncthreads();
    const int warp_off = (wid > 0) ? wsum[wid - 1] : 0;
    const int nun = wsum[31];
    const int scanU = warp_off + eU;
    const int pos = u ? scanU : (nun + (k - scanU));
    g_invp[b * N + pos] = k;
    if (k == 0) g_nun[b] = nun;
}

// ---------------------------------------------------------------------------
// Kernel M: msum[b][k] = sum over MASKED tokens of hs[b][n][k]
// ---------------------------------------------------------------------------
__global__ __launch_bounds__(128) void msum_kernel(
    const float* __restrict__ hs, const int* __restrict__ mask)
{
    __shared__ int mk_s[N];
    const int b = blockIdx.y;
    const int k = blockIdx.x * 128 + threadIdx.x;
    for (int i = threadIdx.x; i < N; i += 128) mk_s[i] = mask[b * N + i];
    __syncthreads();
    float s = 0.0f;
    for (int n = 0; n < N; n++)
        if (mk_s[n]) s += hs[((size_t)b * N + n) * HD + k];
    g_msum[b * HD + k] = s;
}

// ---------------------------------------------------------------------------
// Kernel G: Vsum[b][o] = msum[b] . Wv[o] + nmask * vb[o]
// ---------------------------------------------------------------------------
__global__ __launch_bounds__(256) void vgemm_kernel(
    const float* __restrict__ w, const float* __restrict__ vb)
{
    const int lane = threadIdx.x & 31;
    const int idx = blockIdx.x * 8 + (threadIdx.x >> 5);
    const int b = idx >> 10, o = idx & 1023;
    const float* wr = w + (size_t)(2048 + o) * HD;
    const float* ms = g_msum + b * HD;
    float s = 0.0f;
#pragma unroll
    for (int it = 0; it < 8; it++) {
        int k4 = it * 32 + lane;
        float4 wv = ((const float4*)wr)[k4];
        float4 mv = ((const float4*)ms)[k4];
        s += wv.x * mv.x + wv.y * mv.y + wv.z * mv.z + wv.w * mv.w;
    }
#pragma unroll
    for (int off = 16; off > 0; off >>= 1)
        s += __shfl_xor_sync(0xffffffffu, s, off);
    if (lane == 0) {
        float nm = (float)(N - g_nun[b]);
        g_Vsum[b * HD + o] = s + nm * vb[o];
    }
}

// ---------------------------------------------------------------------------
// Kernel 1: QKV projection, fp16 inputs, cp.async 3-stage pipeline, BK=32,
// ldmatrix fragment loads. 512 threads, tile 128(o) x 256(tok).
// ---------------------------------------------------------------------------
#define QP 20
#define QA_W (128 * QP)
#define QB_W (256 * QP)
#define QS_W (QA_W + QB_W)
#define QKV_DYN_BYTES (3 * QS_W * 4)

__global__ __launch_bounds__(512) void qkv_kernel(
    const float* __restrict__ qb, const float* __restrict__ vb)
{
    extern __shared__ uint32_t sm[];
    __shared__ int invp_s[256];
    const uint32_t smA = smem_u32(sm);

    const int tid  = threadIdx.x;
    const int lane = tid & 31;
    const int warp = tid >> 5;
    const int wo = (warp >> 2) * 32;
    const int wt = (warp & 3) * 64;
    const int o0 = blockIdx.x * 128;
    const int t0 = blockIdx.y * 256;
    const int r = lane >> 2;
    const int c = lane & 3;
    const int b0 = t0 >> 10;
    const int t0l = t0 & 1023;
    const int seg = o0 >> 10;
    const int am = ((lane >> 3) & 1) * 8 + (lane & 7);
    const int ac = (lane >> 4) * 4;

    if (seg != 0) {
        const int ntt = (g_nun[b0] + 255) >> 8;
        if ((t0l >> 8) >= ntt) return;
    }

    if (tid < 256) invp_s[tid] = g_invp[b0 * N + t0l + tid];
    __syncthreads();

    float acc[2][8][4];
#pragma unroll
    for (int g = 0; g < 2; g++)
#pragma unroll
        for (int nj = 0; nj < 8; nj++)
#pragma unroll
            for (int q = 0; q < 4; q++) acc[g][nj][q] = 0.0f;

    auto load_stage = [&](int kc, int buf) {
        const int k0 = kc * 32;
        const uint32_t base = smA + buf * QS_W * 4;
        {
            int row = tid >> 2, f = tid & 3;
            CP_ASYNC16(base + (row * QP + 4 * f) * 4,
                       g_wH + (size_t)(o0 + row) * HD + k0 + 8 * f);
        }
#pragma unroll
        for (int i = 0; i < 2; i++) {
            int slot = tid + 512 * i;
            int row = slot >> 2, f = slot & 3;
            int grow = seg ? (b0 * N + invp_s[row]) : (t0 + row);
            CP_ASYNC16(base + (QA_W + row * QP + 4 * f) * 4,
                       g_hsH + (size_t)grow * HD + k0 + 8 * f);
        }
    };

    load_stage(0, 0); CP_COMMIT();
    load_stage(1, 1); CP_COMMIT();

    for (int kc = 0; kc < 32; kc++) {
        const int buf = kc - (kc / 3) * 3;
        CP_WAIT1();
        __syncthreads();

        if (kc + 2 < 32) load_stage(kc + 2, (kc + 2) - ((kc + 2) / 3) * 3);
        CP_COMMIT();

        const uint32_t Aa = smA + (buf * QS_W) * 4;
        const uint32_t Ba = Aa + QA_W * 4;
#pragma unroll
        for (int ks = 0; ks < 2; ks++) {
            const int kb = ks * 8;
            uint32_t a[2][4], bb[8][2];
#pragma unroll
            for (int g = 0; g < 2; g++)
                ldm4(a[g], Aa + ((wo + 16 * g + am) * QP + kb + ac) * 4);
#pragma unroll
            for (int j = 0; j < 4; j++) {
                uint32_t t4[4];
                ldm4(t4, Ba + ((wt + 16 * j + am) * QP + kb + ac) * 4);
                bb[2 * j][0] = t4[0];     bb[2 * j][1] = t4[2];
                bb[2 * j + 1][0] = t4[1]; bb[2 * j + 1][1] = t4[3];
            }
#pragma unroll
            for (int g = 0; g < 2; g++)
#pragma unroll
                for (int nj = 0; nj < 8; nj++)
                    mma16(acc[g][nj], a[g], bb[nj]);
        }
    }

    // epilogue: contiguous token-row writes
#pragma unroll
    for (int g = 0; g < 2; g++) {
#pragma unroll
        for (int rr = 0; rr < 2; rr++) {
            int o = o0 + wo + 16 * g + r + 8 * rr;
            int hd = o & 1023, h = hd >> 6, d = hd & 63;
            float addb = (seg == 0) ? qb[hd] : ((seg == 2) ? vb[hd] : 0.0f);
#pragma unroll
            for (int nj = 0; nj < 8; nj++) {
                int tokl = wt + 8 * nj + 2 * c;
                int n = t0l + tokl;
                float v0 = acc[g][nj][2 * rr + 0];
                float v1 = acc[g][nj][2 * rr + 1];
                size_t idx = (((size_t)(b0 * H + h)) * N + n) * D + d;
                if (seg == 0) {
                    g_Qh[idx]     = __float2half((v0 + addb) * 0.125f);
                    g_Qh[idx + D] = __float2half((v1 + addb) * 0.125f);
                } else if (seg == 1) {
                    g_Kh[idx]     = __float2half(v0);
                    g_Kh[idx + D] = __float2half(v1);
                } else {
                    g_Vh[idx]     = __float2half(v0 + addb);
                    g_Vh[idx + D] = __float2half(v1 + addb);
                }
            }
        }
    }
}

// ---------------------------------------------------------------------------
// Kernel 2: flash attention. P in registers, ldmatrix frags, paired bias
// loads (LDG.64 fetches rows r and r+8 of one gathered column). 2 CTAs/SM.
// ---------------------------------------------------------------------------
#define AT_PITCH 36
#define AT_KW (64 * AT_PITCH)
#define AT_DYN_BYTES ((4 * AT_KW + N) * 4)

__global__ __launch_bounds__(256, 2) void attn_kernel(float* __restrict__ out)
{
    extern __shared__ uint32_t dynsm[];
    int* invp_s = (int*)(dynsm + 4 * AT_KW);
    const uint32_t dynA = smem_u32(dynsm);

    const int tid  = threadIdx.x;
    const int lane = tid & 31;
    const int warp = tid >> 5;
    const int q0 = blockIdx.x * 128;
    const int h  = blockIdx.y;
    const int b  = blockIdx.z;
    const int qw = warp * 16;
    const int r = lane >> 2;
    const int c = lane & 3;
    const int am = ((lane >> 3) & 1) * 8 + (lane & 7);
    const int ac = (lane >> 4) * 4;

    const __half* Qh = g_Qh + (size_t)(b * H + h) * N * D;
    const __half* Kh = g_Kh + (size_t)(b * H + h) * N * D;
    const __half* Vh = g_Vh + (size_t)(b * H + h) * N * D;
    // paired bias: rbp[c0*N] = float2{ RB[row0][c0], RB[row0+8][c0] }
    const float* rbp = g_RBp + (size_t)h * N * N + (q0 + qw + 2 * r);

    const int nun = g_nun[b];
    const int ntiles = (nun + 63) >> 6;

    for (int i = tid; i < N; i += 256) invp_s[i] = g_invp[b * N + i];

    // stage Q tile (128 x 64) through the K-tile smem, lift fragments
#pragma unroll
    for (int i = 0; i < 4; i++) {
        int slot = tid + 256 * i;
        int row = slot >> 3, j = slot & 7;
        uint4 v = ((const uint4*)(Qh + (size_t)(q0 + row) * D))[j];
        STS128V(dynA + (row * AT_PITCH + 4 * j) * 4, v);
    }
    __syncthreads();

    uint32_t qa[4][4];
#pragma unroll
    for (int ks = 0; ks < 4; ks++)
        ldm4(qa[ks], dynA + ((qw + am) * AT_PITCH + 8 * ks + ac) * 4);
    __syncthreads();   // Q frags read; smem free for K/V pipeline

    auto load_tile = [&](int t, int buf) {
        const int k0 = t * 64;
        const uint32_t kb = dynA + (buf * AT_KW) * 4;
        const uint32_t vbuf = dynA + ((2 + buf) * AT_KW) * 4;
#pragma unroll
        for (int i = 0; i < 2; i++) {
            int slot = tid + 256 * i;
            int row = slot >> 3, j = slot & 7;
            CP_ASYNC16(kb + (row * AT_PITCH + 4 * j) * 4,
                       Kh + (size_t)(k0 + row) * D + 8 * j);
            CP_ASYNC16(vbuf + (row * AT_PITCH + 4 * j) * 4,
                       Vh + (size_t)(k0 + row) * D + 8 * j);
        }
    };

    float m0v = -INFINITY, m1v = -INFINITY, l0 = 0.0f, l1 = 0.0f;
    float oacc[8][4];
#pragma unroll
    for (int nb = 0; nb < 8; nb++)
#pragma unroll
        for (int q = 0; q < 4; q++) oacc[nb][q] = 0.0f;

    load_tile(0, 0);
    CP_COMMIT();

    for (int t = 0; t < ntiles; t++) {
        const int buf = t & 1;
        const int k0 = t * 64;
        CP_WAIT0();
        __syncthreads();

        if (t + 1 < ntiles) {
            load_tile(t + 1, buf ^ 1);
            CP_COMMIT();
        }

        const uint32_t KsA = dynA + (buf * AT_KW) * 4;
        const uint32_t vldm = dynA + ((2 + buf) * AT_KW + (lane & 15) * AT_PITCH) * 4;

        // S = Q @ K^T  (K-frags via ldmatrix)
        float sacc[8][4];
#pragma unroll
        for (int nb = 0; nb < 8; nb++)
#pragma unroll
            for (int q = 0; q < 4; q++) sacc[nb][q] = 0.0f;

#pragma unroll
        for (int ks = 0; ks < 4; ks++) {
#pragma unroll
            for (int j = 0; j < 4; j++) {
                uint32_t t4[4];
                ldm4(t4, KsA + ((16 * j + am) * AT_PITCH + 8 * ks + ac) * 4);
                uint32_t b0[2] = {t4[0], t4[2]};
                uint32_t b1[2] = {t4[1], t4[3]};
                mma16(sacc[2 * j],     qa[ks], b0);
                mma16(sacc[2 * j + 1], qa[ks], b1);
            }
        }

        // paired bias + tail cut + row max
        float rmax0 = -INFINITY, rmax1 = -INFINITY;
#pragma unroll
        for (int nb = 0; nb < 8; nb++) {
            int p0 = k0 + 8 * nb + 2 * c;
            int c0 = invp_s[p0], c1 = invp_s[p0 + 1];
            float2 bz0 = *(const float2*)&rbp[(size_t)c0 * N];
            float2 bz1 = *(const float2*)&rbp[(size_t)c1 * N];
            float s0 = sacc[nb][0] + bz0.x;
            float s1 = sacc[nb][1] + bz1.x;
            float s2 = sacc[nb][2] + bz0.y;
            float s3 = sacc[nb][3] + bz1.y;
            if (p0 >= nun)     { s0 = -1e30f; s2 = -1e30f; }
            if (p0 + 1 >= nun) { s1 = -1e30f; s3 = -1e30f; }
            sacc[nb][0] = s0; sacc[nb][1] = s1; sacc[nb][2] = s2; sacc[nb][3] = s3;
            rmax0 = fmaxf(rmax0, fmaxf(s0, s1));
            rmax1 = fmaxf(rmax1, fmaxf(s2, s3));
        }
        rmax0 = fmaxf(rmax0, __shfl_xor_sync(0xffffffffu, rmax0, 1));
        rmax0 = fmaxf(rmax0, __shfl_xor_sync(0xffffffffu, rmax0, 2));
        rmax1 = fmaxf(rmax1, __shfl_xor_sync(0xffffffffu, rmax1, 1));
        rmax1 = fmaxf(rmax1, __shfl_xor_sync(0xffffffffu, rmax1, 2));

        float mn0 = fmaxf(m0v, rmax0), mn1 = fmaxf(m1v, rmax1);
        float sc0 = __expf(m0v - mn0), sc1 = __expf(m1v - mn1);
        m0v = mn0; m1v = mn1;

        // exp -> P directly into A-fragment registers
        uint32_t ph[8][2];
        float rs0 = 0.0f, rs1 = 0.0f;
#pragma unroll
        for (int nb = 0; nb < 8; nb++) {
            float p0 = __expf(sacc[nb][0] - mn0);
            float p1 = __expf(sacc[nb][1] - mn0);
            float p2 = __expf(sacc[nb][2] - mn1);
            float p3 = __expf(sacc[nb][3] - mn1);
            rs0 += p0 + p1;
            rs1 += p2 + p3;
            ph[nb][0] = f2h2(p0, p1);
            ph[nb][1] = f2h2(p2, p3);
        }
        rs0 += __shfl_xor_sync(0xffffffffu, rs0, 1);
        rs0 += __shfl_xor_sync(0xffffffffu, rs0, 2);
        rs1 += __shfl_xor_sync(0xffffffffu, rs1, 1);
        rs1 += __shfl_xor_sync(0xffffffffu, rs1, 2);
        l0 = l0 * sc0 + rs0;
        l1 = l1 * sc1 + rs1;
#pragma unroll
        for (int nb = 0; nb < 8; nb++) {
            oacc[nb][0] *= sc0; oacc[nb][1] *= sc0;
            oacc[nb][2] *= sc1; oacc[nb][3] *= sc1;
        }

        // O += P @ V   (P from registers; V B-frags via ldmatrix.trans)
#pragma unroll
        for (int ks = 0; ks < 4; ks++) {
            uint32_t pa[4];
            pa[0] = ph[2 * ks][0];
            pa[1] = ph[2 * ks][1];
            pa[2] = ph[2 * ks + 1][0];
            pa[3] = ph[2 * ks + 1][1];
            const uint32_t vbase = vldm + (16 * ks * AT_PITCH) * 4;
#pragma unroll
            for (int nb = 0; nb < 8; nb++) {
                uint32_t bbv[2];
                ldm2t(bbv, vbase + nb * 16);
                mma16(oacc[nb], pa, bbv);
            }
        }
    }

    // analytic masked-key correction
    const int nmask = N - nun;
    float cM0 = 0.0f, cM1 = 0.0f;
    if (nmask > 0) {
        float mf0 = fmaxf(m0v, 1e-8f), mf1 = fmaxf(m1v, 1e-8f);
        float sc0 = __expf(m0v - mf0), sc1 = __expf(m1v - mf1);
        float pm0 = __expf(1e-8f - mf0), pm1 = __expf(1e-8f - mf1);
        l0 = l0 * sc0 + (float)nmask * pm0;
        l1 = l1 * sc1 + (float)nmask * pm1;
        cM0 = pm0; cM1 = pm1;
#pragma unroll
        for (int nb = 0; nb < 8; nb++) {
            oacc[nb][0] *= sc0; oacc[nb][1] *= sc0;
            oacc[nb][2] *= sc1; oacc[nb][3] *= sc1;
        }
    }

    const float* vs = g_Vsum + b * HD + h * D;
    const float inv0 = 1.0f / l0, inv1 = 1.0f / l1;
    const int n0_ = q0 + qw + r;
#pragma unroll
    for (int nb = 0; nb < 8; nb++) {
        int d = 8 * nb + 2 * c;
        float2 vv = *(const float2*)&vs[d];
        float2 v0; v0.x = (oacc[nb][0] + cM0 * vv.x) * inv0;
        v0.y = (oacc[nb][1] + cM0 * vv.y) * inv0;
        *(float2*)&out[((size_t)b * N + n0_) * HD + h * D + d] = v0;
        float2 v1; v1.x = (oacc[nb][2] + cM1 * vv.x) * inv1;
        v1.y = (oacc[nb][3] + cM1 * vv.y) * inv1;
        *(float2*)&out[((size_t)b * N + n0_ + 8) * HD + h * D + d] = v1;
    }
}

extern "C" void kernel_launch(void* const* d_in, const int* in_sizes, int n_in,
                              void* d_out, int out_size)
{
    (void)in_sizes; (void)n_in; (void)out_size;
    const float* hs   = (const float*)d_in[0];
    const float* w    = (const float*)d_in[1];
    const float* qb   = (const float*)d_in[2];
    const float* vb   = (const float*)d_in[3];
    const float* rel  = (const float*)d_in[4];
    const float* rel2 = (const float*)d_in[5];
    const int*   mask = (const int*)d_in[6];
    float* out = (float*)d_out;

    cudaFuncSetAttribute(qkv_kernel,
                         cudaFuncAttributeMaxDynamicSharedMemorySize, QKV_DYN_BYTES);
    cudaFuncSetAttribute(attn_kernel,
                         cudaFuncAttributeMaxDynamicSharedMemorySize, AT_DYN_BYTES);

    cvt_hs_kernel<<<(B * N * HD) / (256 * 8), 256>>>(hs);
    cvt_w_kernel<<<(3 * HD * HD) / (256 * 8), 256>>>(w);
    biasT_kernel<<<dim3(16, 16, 16), 256>>>(rel, rel2);
    perm_kernel<<<B, 1024>>>(mask);
    msum_kernel<<<dim3(8, B), 128>>>(hs, mask);

    dim3 g1(3 * HD / 128, (B * N) / 256);        // (24, 32)
    qkv_kernel<<<g1, 512, QKV_DYN_BYTES>>>(qb, vb);

    vgemm_kernel<<<1024, 256>>>(w, vb);

    dim3 g2(N / 128, H, B);                      // (8, 16, 8)
    attn_kernel<<<g2, 256, AT_DYN_BYTES>>>(out);
}

// round 16
// speedup vs baseline: 1.6118x; 1.4841x over previous
#include <cuda_runtime.h>
#include <cuda_fp16.h>
#include <math.h>
#include <stdint.h>

#define B 8
#define N 1024
#define H 16
#define D 64
#define HD 1024

// Scratch (allocation-free)
__device__ __half g_hsH[B * N * HD];       // fp16 copy of hidden_states
__device__ __half g_wH[3 * HD * HD];       // fp16 copy of qkv_w
__device__ __half g_Qh[B * H * N * D];     // original token order, *0.125
__device__ __half g_Kh[B * H * N * D];     // keys compacted (unmasked first)
__device__ __half g_Vh[B * H * N * D];     // [np][d] row-major, compacted
__device__ float  g_RB[H * N * N];         // combined bias, ORIGINAL key order
__device__ int    g_invp[B * N];           // permuted pos -> orig key
__device__ int    g_nun[B];                // # unmasked keys
__device__ float  g_msum4[4 * B * HD];     // 4 n-chunk partials of masked hs sum
__device__ float  g_Vsum[B * HD];          // sum of V over masked keys (fp32)

__device__ __forceinline__ uint32_t f2h2(float lo, float hi) {
    __half2 h = __floats2half2_rn(lo, hi);
    return *(uint32_t*)&h;
}

__device__ __forceinline__ void mma16(float* d, const uint32_t* a, const uint32_t* b) {
    asm volatile(
        "mma.sync.aligned.m16n8k16.row.col.f32.f16.f16.f32 "
        "{%0,%1,%2,%3}, {%4,%5,%6,%7}, {%8,%9}, {%0,%1,%2,%3};"
        : "+f"(d[0]), "+f"(d[1]), "+f"(d[2]), "+f"(d[3])
        : "r"(a[0]), "r"(a[1]), "r"(a[2]), "r"(a[3]), "r"(b[0]), "r"(b[1]));
}

__device__ __forceinline__ void ldm4(uint32_t* d, uint32_t a) {
    asm volatile("ldmatrix.sync.aligned.m8n8.x4.shared.b16 {%0,%1,%2,%3}, [%4];"
        : "=r"(d[0]), "=r"(d[1]), "=r"(d[2]), "=r"(d[3]) : "r"(a));
}

__device__ __forceinline__ void ldm2t(uint32_t* d, uint32_t a) {
    asm volatile("ldmatrix.sync.aligned.m8n8.x2.trans.shared.b16 {%0,%1}, [%2];"
        : "=r"(d[0]), "=r"(d[1]) : "r"(a));
}

#define STS128V(addr, u) asm volatile("st.shared.v4.b32 [%0], {%1,%2,%3,%4};" \
    :: "r"(addr), "r"((u).x), "r"((u).y), "r"((u).z), "r"((u).w) : "memory")
#define CP_ASYNC16(dst, src) asm volatile( \
    "cp.async.cg.shared.global [%0], [%1], 16;" :: "r"(dst), "l"(src) : "memory")
#define CP_COMMIT() asm volatile("cp.async.commit_group;" ::: "memory")
#define CP_WAIT0()  asm volatile("cp.async.wait_group 0;" ::: "memory")
#define CP_WAIT1()  asm volatile("cp.async.wait_group 1;" ::: "memory")

__device__ __forceinline__ uint32_t smem_u32(const void* p) {
    uint32_t a;
    asm("{ .reg .u64 t; cvta.to.shared.u64 t, %1; cvt.u32.u64 %0, t; }"
        : "=r"(a) : "l"(p));
    return a;
}

// ---------------------------------------------------------------------------
// Kernel 0: combined bias = rel_pos + rel_2d_pos (row-major, as in round 12)
// ---------------------------------------------------------------------------
__global__ __launch_bounds__(256) void bias_kernel(
    const float* __restrict__ rel, const float* __restrict__ rel2)
{
    size_t i = ((size_t)blockIdx.x * 256 + threadIdx.x) * 4;
    float4 a = *(const float4*)&rel[i];
    float4 b = *(const float4*)&rel2[i];
    a.x += b.x; a.y += b.y; a.z += b.z; a.w += b.w;
    *(float4*)&g_RB[i] = a;
}

// ---------------------------------------------------------------------------
// Kernel C: fused fp32 -> fp16 conversion of hs (blocks < 4096) and W (rest)
// ---------------------------------------------------------------------------
__global__ __launch_bounds__(256) void cvt_kernel(
    const float* __restrict__ hs, const float* __restrict__ w)
{
    const int bx = blockIdx.x;
    const float* src;
    __half* dst;
    size_t i;
    if (bx < 4096) {            // hs: 8M elems / (256*8)
        i = ((size_t)bx * 256 + threadIdx.x) * 8;
        src = hs; dst = g_hsH;
    } else {                    // w: 3M elems
        i = ((size_t)(bx - 4096) * 256 + threadIdx.x) * 8;
        src = w; dst = g_wH;
    }
    float4 a = *(const float4*)&src[i];
    float4 b = *(const float4*)&src[i + 4];
    uint4 u;
    u.x = f2h2(a.x, a.y); u.y = f2h2(a.z, a.w);
    u.z = f2h2(b.x, b.y); u.w = f2h2(b.z, b.w);
    *(uint4*)&dst[i] = u;
}

// ---------------------------------------------------------------------------
// Kernel P: stable partition of keys per batch (unmasked first).
// ---------------------------------------------------------------------------
__global__ __launch_bounds__(1024) void perm_kernel(const int* __restrict__ mask)
{
    const int b = blockIdx.x, k = threadIdx.x;
    const int lane = k & 31, wid = k >> 5;
    const int u = (mask[b * N + k] == 0) ? 1 : 0;
    unsigned bal = __ballot_sync(0xffffffffu, u);
    int eU = __popc(bal & ((1u << lane) - 1));

    __shared__ int wsum[32];
    if (lane == 31) wsum[wid] = eU + u;
    __syncthreads();
    if (wid == 0) {
        int v = wsum[lane];
#pragma unroll
        for (int off = 1; off < 32; off <<= 1) {
            int t = __shfl_up_sync(0xffffffffu, v, off);
            if (lane >= off) v += t;
        }
        wsum[lane] = v;
    }
    __syncthreads();
    const int warp_off = (wid > 0) ? wsum[wid - 1] : 0;
    const int nun = wsum[31];
    const int scanU = warp_off + eU;
    const int pos = u ? scanU : (nun + (k - scanU));
    g_invp[b * N + pos] = k;
    if (k == 0) g_nun[b] = nun;
}

// ---------------------------------------------------------------------------
// Kernel M: 4-way n-split masked hs sums (partials; no atomics)
// grid (8 k-chunks, B, 4 n-chunks), 128 threads
// ---------------------------------------------------------------------------
__global__ __launch_bounds__(128) void msum_kernel(
    const float* __restrict__ hs, const int* __restrict__ mask)
{
    __shared__ int mk_s[256];
    const int b = blockIdx.y;
    const int z = blockIdx.z;
    const int n0 = z * 256;
    const int k = blockIdx.x * 128 + threadIdx.x;
    for (int i = threadIdx.x; i < 256; i += 128) mk_s[i] = mask[b * N + n0 + i];
    __syncthreads();
    float s = 0.0f;
#pragma unroll 4
    for (int n = 0; n < 256; n++)
        if (mk_s[n]) s += hs[((size_t)b * N + n0 + n) * HD + k];
    g_msum4[((size_t)z * B + b) * HD + k] = s;
}

// ---------------------------------------------------------------------------
// Kernel G: Vsum[b][o] = (sum of msum partials) . Wv[o] + nmask * vb[o]
// ---------------------------------------------------------------------------
__global__ __launch_bounds__(256) void vgemm_kernel(
    const float* __restrict__ w, const float* __restrict__ vb)
{
    const int lane = threadIdx.x & 31;
    const int idx = blockIdx.x * 8 + (threadIdx.x >> 5);
    const int b = idx >> 10, o = idx & 1023;
    const float* wr = w + (size_t)(2048 + o) * HD;
    const float* m0 = g_msum4 + (size_t)b * HD;
    const float* m1 = m0 + (size_t)B * HD;
    const float* m2 = m1 + (size_t)B * HD;
    const float* m3 = m2 + (size_t)B * HD;
    float s = 0.0f;
#pragma unroll
    for (int it = 0; it < 8; it++) {
        int k4 = it * 32 + lane;
        float4 wv = ((const float4*)wr)[k4];
        float4 a = ((const float4*)m0)[k4];
        float4 c = ((const float4*)m1)[k4];
        float4 d = ((const float4*)m2)[k4];
        float4 e = ((const float4*)m3)[k4];
        float4 mv;
        mv.x = a.x + c.x + d.x + e.x;
        mv.y = a.y + c.y + d.y + e.y;
        mv.z = a.z + c.z + d.z + e.z;
        mv.w = a.w + c.w + d.w + e.w;
        s += wv.x * mv.x + wv.y * mv.y + wv.z * mv.z + wv.w * mv.w;
    }
#pragma unroll
    for (int off = 16; off > 0; off >>= 1)
        s += __shfl_xor_sync(0xffffffffu, s, off);
    if (lane == 0) {
        float nm = (float)(N - g_nun[b]);
        g_Vsum[b * HD + o] = s + nm * vb[o];
    }
}

// ---------------------------------------------------------------------------
// Kernel 1: QKV projection, fp16 inputs, cp.async 3-stage pipeline, BK=32,
// ldmatrix fragment loads. 512 threads, tile 128(o) x 256(tok).  (round 12)
// ---------------------------------------------------------------------------
#define QP 20
#define QA_W (128 * QP)
#define QB_W (256 * QP)
#define QS_W (QA_W + QB_W)
#define QKV_DYN_BYTES (3 * QS_W * 4)

__global__ __launch_bounds__(512) void qkv_kernel(
    const float* __restrict__ qb, const float* __restrict__ vb)
{
    extern __shared__ uint32_t sm[];
    __shared__ int invp_s[256];
    const uint32_t smA = smem_u32(sm);

    const int tid  = threadIdx.x;
    const int lane = tid & 31;
    const int warp = tid >> 5;
    const int wo = (warp >> 2) * 32;
    const int wt = (warp & 3) * 64;
    const int o0 = blockIdx.x * 128;
    const int t0 = blockIdx.y * 256;
    const int r = lane >> 2;
    const int c = lane & 3;
    const int b0 = t0 >> 10;
    const int t0l = t0 & 1023;
    const int seg = o0 >> 10;
    const int am = ((lane >> 3) & 1) * 8 + (lane & 7);
    const int ac = (lane >> 4) * 4;

    if (seg != 0) {
        const int ntt = (g_nun[b0] + 255) >> 8;
        if ((t0l >> 8) >= ntt) return;
    }

    if (tid < 256) invp_s[tid] = g_invp[b0 * N + t0l + tid];
    __syncthreads();

    float acc[2][8][4];
#pragma unroll
    for (int g = 0; g < 2; g++)
#pragma unroll
        for (int nj = 0; nj < 8; nj++)
#pragma unroll
            for (int q = 0; q < 4; q++) acc[g][nj][q] = 0.0f;

    auto load_stage = [&](int kc, int buf) {
        const int k0 = kc * 32;
        const uint32_t base = smA + buf * QS_W * 4;
        {
            int row = tid >> 2, f = tid & 3;
            CP_ASYNC16(base + (row * QP + 4 * f) * 4,
                       g_wH + (size_t)(o0 + row) * HD + k0 + 8 * f);
        }
#pragma unroll
        for (int i = 0; i < 2; i++) {
            int slot = tid + 512 * i;
            int row = slot >> 2, f = slot & 3;
            int grow = seg ? (b0 * N + invp_s[row]) : (t0 + row);
            CP_ASYNC16(base + (QA_W + row * QP + 4 * f) * 4,
                       g_hsH + (size_t)grow * HD + k0 + 8 * f);
        }
    };

    load_stage(0, 0); CP_COMMIT();
    load_stage(1, 1); CP_COMMIT();

    for (int kc = 0; kc < 32; kc++) {
        const int buf = kc - (kc / 3) * 3;
        CP_WAIT1();
        __syncthreads();

        if (kc + 2 < 32) load_stage(kc + 2, (kc + 2) - ((kc + 2) / 3) * 3);
        CP_COMMIT();

        const uint32_t Aa = smA + (buf * QS_W) * 4;
        const uint32_t Ba = Aa + QA_W * 4;
#pragma unroll
        for (int ks = 0; ks < 2; ks++) {
            const int kb = ks * 8;
            uint32_t a[2][4], bb[8][2];
#pragma unroll
            for (int g = 0; g < 2; g++)
                ldm4(a[g], Aa + ((wo + 16 * g + am) * QP + kb + ac) * 4);
#pragma unroll
            for (int j = 0; j < 4; j++) {
                uint32_t t4[4];
                ldm4(t4, Ba + ((wt + 16 * j + am) * QP + kb + ac) * 4);
                bb[2 * j][0] = t4[0];     bb[2 * j][1] = t4[2];
                bb[2 * j + 1][0] = t4[1]; bb[2 * j + 1][1] = t4[3];
            }
#pragma unroll
            for (int g = 0; g < 2; g++)
#pragma unroll
                for (int nj = 0; nj < 8; nj++)
                    mma16(acc[g][nj], a[g], bb[nj]);
        }
    }

    // epilogue: contiguous token-row writes
#pragma unroll
    for (int g = 0; g < 2; g++) {
#pragma unroll
        for (int rr = 0; rr < 2; rr++) {
            int o = o0 + wo + 16 * g + r + 8 * rr;
            int hd = o & 1023, h = hd >> 6, d = hd & 63;
            float addb = (seg == 0) ? qb[hd] : ((seg == 2) ? vb[hd] : 0.0f);
#pragma unroll
            for (int nj = 0; nj < 8; nj++) {
                int tokl = wt + 8 * nj + 2 * c;
                int n = t0l + tokl;
                float v0 = acc[g][nj][2 * rr + 0];
                float v1 = acc[g][nj][2 * rr + 1];
                size_t idx = (((size_t)(b0 * H + h)) * N + n) * D + d;
                if (seg == 0) {
                    g_Qh[idx]     = __float2half((v0 + addb) * 0.125f);
                    g_Qh[idx + D] = __float2half((v1 + addb) * 0.125f);
                } else if (seg == 1) {
                    g_Kh[idx]     = __float2half(v0);
                    g_Kh[idx + D] = __float2half(v1);
                } else {
                    g_Vh[idx]     = __float2half(v0 + addb);
                    g_Vh[idx + D] = __float2half(v1 + addb);
                }
            }
        }
    }
}

// ---------------------------------------------------------------------------
// Kernel 2: flash attention (round-12 version): cp.async double-buffered K/V,
// P through smem, row-major gathered bias, analytic masked fix. 2 CTAs/SM.
// ---------------------------------------------------------------------------
#define AT_PITCH 36
#define AT_KW (64 * AT_PITCH)
#define AT_PSW (128 * AT_PITCH)
#define AT_DYN_BYTES ((4 * AT_KW + AT_PSW + N) * 4)

__global__ __launch_bounds__(256, 2) void attn_kernel(float* __restrict__ out)
{
    extern __shared__ uint32_t dynsm[];
    uint32_t* Ps = dynsm + 4 * AT_KW;
    int* invp_s = (int*)(dynsm + 4 * AT_KW + AT_PSW);
    const uint32_t dynA = smem_u32(dynsm);
    const uint32_t PsA  = dynA + 4 * AT_KW * 4;

    const int tid  = threadIdx.x;
    const int lane = tid & 31;
    const int warp = tid >> 5;
    const int q0 = blockIdx.x * 128;
    const int h  = blockIdx.y;
    const int b  = blockIdx.z;
    const int qw = warp * 16;
    const int r = lane >> 2;
    const int c = lane & 3;

    const __half* Qh = g_Qh + (size_t)(b * H + h) * N * D;
    const __half* Kh = g_Kh + (size_t)(b * H + h) * N * D;
    const __half* Vh = g_Vh + (size_t)(b * H + h) * N * D;
    const float*  rb = g_RB + (size_t)h * N * N;

    const int nun = g_nun[b];
    const int ntiles = (nun + 63) >> 6;

    for (int i = tid; i < N; i += 256) invp_s[i] = g_invp[b * N + i];

#pragma unroll
    for (int i = 0; i < 4; i++) {
        int slot = lane + 32 * i;
        int row16 = slot >> 3, j = slot & 7;
        uint4 v = ((const uint4*)(Qh + (size_t)(q0 + qw + row16) * D))[j];
        STS128V(PsA + ((qw + row16) * AT_PITCH + 4 * j) * 4, v);
    }
    __syncwarp();

    uint32_t qa[4][4];
#pragma unroll
    for (int ks = 0; ks < 4; ks++) {
        qa[ks][0] = Ps[(qw + r) * AT_PITCH + 8 * ks + c];
        qa[ks][1] = Ps[(qw + r + 8) * AT_PITCH + 8 * ks + c];
        qa[ks][2] = Ps[(qw + r) * AT_PITCH + 8 * ks + c + 4];
        qa[ks][3] = Ps[(qw + r + 8) * AT_PITCH + 8 * ks + c + 4];
    }

    auto load_tile = [&](int t, int buf) {
        const int k0 = t * 64;
        const uint32_t kb = dynA + (buf * AT_KW) * 4;
        const uint32_t vbuf = dynA + ((2 + buf) * AT_KW) * 4;
#pragma unroll
        for (int i = 0; i < 2; i++) {
            int slot = tid + 256 * i;
            int row = slot >> 3, j = slot & 7;
            CP_ASYNC16(kb + (row * AT_PITCH + 4 * j) * 4,
                       Kh + (size_t)(k0 + row) * D + 8 * j);
            CP_ASYNC16(vbuf + (row * AT_PITCH + 4 * j) * 4,
                       Vh + (size_t)(k0 + row) * D + 8 * j);
        }
    };

    float m0v = -INFINITY, m1v = -INFINITY, l0 = 0.0f, l1 = 0.0f;
    float oacc[8][4];
#pragma unroll
    for (int nb = 0; nb < 8; nb++)
#pragma unroll
        for (int q = 0; q < 4; q++) oacc[nb][q] = 0.0f;

    load_tile(0, 0);
    CP_COMMIT();

    for (int t = 0; t < ntiles; t++) {
        const int buf = t & 1;
        const int k0 = t * 64;
        CP_WAIT0();
        __syncthreads();

        if (t + 1 < ntiles) {
            load_tile(t + 1, buf ^ 1);
            CP_COMMIT();
        }

        const uint32_t* Ks = dynsm + buf * AT_KW;
        const uint32_t vldm = dynA + ((2 + buf) * AT_KW + (lane & 15) * AT_PITCH) * 4;

        float sacc[8][4];
#pragma unroll
        for (int nb = 0; nb < 8; nb++)
#pragma unroll
            for (int q = 0; q < 4; q++) sacc[nb][q] = 0.0f;

#pragma unroll
        for (int ks = 0; ks < 4; ks++) {
            uint32_t bbk[8][2];
#pragma unroll
            for (int nb = 0; nb < 8; nb++) {
                bbk[nb][0] = Ks[(8 * nb + r) * AT_PITCH + 8 * ks + c];
                bbk[nb][1] = Ks[(8 * nb + r) * AT_PITCH + 8 * ks + c + 4];
            }
#pragma unroll
            for (int nb = 0; nb < 8; nb++) mma16(sacc[nb], qa[ks], bbk[nb]);
        }

        const int row0 = q0 + qw + r;
        float rmax0 = -INFINITY, rmax1 = -INFINITY;
#pragma unroll
        for (int nb = 0; nb < 8; nb++) {
            int p0 = k0 + 8 * nb + 2 * c;
            int c0 = invp_s[p0], c1 = invp_s[p0 + 1];
            float s0 = sacc[nb][0] + rb[(size_t)row0 * N + c0];
            float s1 = sacc[nb][1] + rb[(size_t)row0 * N + c1];
            float s2 = sacc[nb][2] + rb[(size_t)(row0 + 8) * N + c0];
            float s3 = sacc[nb][3] + rb[(size_t)(row0 + 8) * N + c1];
            if (p0 >= nun)     { s0 = -1e30f; s2 = -1e30f; }
            if (p0 + 1 >= nun) { s1 = -1e30f; s3 = -1e30f; }
            sacc[nb][0] = s0; sacc[nb][1] = s1; sacc[nb][2] = s2; sacc[nb][3] = s3;
            rmax0 = fmaxf(rmax0, fmaxf(s0, s1));
            rmax1 = fmaxf(rmax1, fmaxf(s2, s3));
        }
        rmax0 = fmaxf(rmax0, __shfl_xor_sync(0xffffffffu, rmax0, 1));
        rmax0 = fmaxf(rmax0, __shfl_xor_sync(0xffffffffu, rmax0, 2));
        rmax1 = fmaxf(rmax1, __shfl_xor_sync(0xffffffffu, rmax1, 1));
        rmax1 = fmaxf(rmax1, __shfl_xor_sync(0xffffffffu, rmax1, 2));

        float mn0 = fmaxf(m0v, rmax0), mn1 = fmaxf(m1v, rmax1);
        float sc0 = __expf(m0v - mn0), sc1 = __expf(m1v - mn1);
        m0v = mn0; m1v = mn1;

        float rs0 = 0.0f, rs1 = 0.0f;
#pragma unroll
        for (int nb = 0; nb < 8; nb++) {
            float p0 = __expf(sacc[nb][0] - mn0);
            float p1 = __expf(sacc[nb][1] - mn0);
            float p2 = __expf(sacc[nb][2] - mn1);
            float p3 = __expf(sacc[nb][3] - mn1);
            rs0 += p0 + p1;
            rs1 += p2 + p3;
            Ps[(qw + r) * AT_PITCH + 4 * nb + c]     = f2h2(p0, p1);
            Ps[(qw + r + 8) * AT_PITCH + 4 * nb + c] = f2h2(p2, p3);
        }
        rs0 += __shfl_xor_sync(0xffffffffu, rs0, 1);
        rs0 += __shfl_xor_sync(0xffffffffu, rs0, 2);
        rs1 += __shfl_xor_sync(0xffffffffu, rs1, 1);
        rs1 += __shfl_xor_sync(0xffffffffu, rs1, 2);
        l0 = l0 * sc0 + rs0;
        l1 = l1 * sc1 + rs1;
#pragma unroll
        for (int nb = 0; nb < 8; nb++) {
            oacc[nb][0] *= sc0; oacc[nb][1] *= sc0;
            oacc[nb][2] *= sc1; oacc[nb][3] *= sc1;
        }
        __syncwarp();

#pragma unroll
        for (int ks = 0; ks < 4; ks++) {
            uint32_t pa[4];
            pa[0] = Ps[(qw + r) * AT_PITCH + 8 * ks + c];
            pa[1] = Ps[(qw + r + 8) * AT_PITCH + 8 * ks + c];
            pa[2] = Ps[(qw + r) * AT_PITCH + 8 * ks + c + 4];
            pa[3] = Ps[(qw + r + 8) * AT_PITCH + 8 * ks + c + 4];
            const uint32_t vbase = vldm + (16 * ks * AT_PITCH) * 4;
#pragma unroll
            for (int nb = 0; nb < 8; nb++) {
                uint32_t bbv[2];
                ldm2t(bbv, vbase + nb * 16);
                mma16(oacc[nb], pa, bbv);
            }
        }
    }

    const int nmask = N - nun;
    float cM0 = 0.0f, cM1 = 0.0f;
    if (nmask > 0) {
        float mf0 = fmaxf(m0v, 1e-8f), mf1 = fmaxf(m1v, 1e-8f);
        float sc0 = __expf(m0v - mf0), sc1 = __expf(m1v - mf1);
        float pm0 = __expf(1e-8f - mf0), pm1 = __expf(1e-8f - mf1);
        l0 = l0 * sc0 + (float)nmask * pm0;
        l1 = l1 * sc1 + (float)nmask * pm1;
        cM0 = pm0; cM1 = pm1;
#pragma unroll
        for (int nb = 0; nb < 8; nb++) {
            oacc[nb][0] *= sc0; oacc[nb][1] *= sc0;
            oacc[nb][2] *= sc1; oacc[nb][3] *= sc1;
        }
    }

    const float* vs = g_Vsum + b * HD + h * D;
    const float inv0 = 1.0f / l0, inv1 = 1.0f / l1;
    const int n0_ = q0 + qw + r;
#pragma unroll
    for (int nb = 0; nb < 8; nb++) {
        int d = 8 * nb + 2 * c;
        float2 vv = *(const float2*)&vs[d];
        float2 v0; v0.x = (oacc[nb][0] + cM0 * vv.x) * inv0;
        v0.y = (oacc[nb][1] + cM0 * vv.y) * inv0;
        *(float2*)&out[((size_t)b * N + n0_) * HD + h * D + d] = v0;
        float2 v1; v1.x = (oacc[nb][2] + cM1 * vv.x) * inv1;
        v1.y = (oacc[nb][3] + cM1 * vv.y) * inv1;
        *(float2*)&out[((size_t)b * N + n0_ + 8) * HD + h * D + d] = v1;
    }
}

extern "C" void kernel_launch(void* const* d_in, const int* in_sizes, int n_in,
                              void* d_out, int out_size)
{
    (void)in_sizes; (void)n_in; (void)out_size;
    const float* hs   = (const float*)d_in[0];
    const float* w    = (const float*)d_in[1];
    const float* qb   = (const float*)d_in[2];
    const float* vb   = (const float*)d_in[3];
    const float* rel  = (const float*)d_in[4];
    const float* rel2 = (const float*)d_in[5];
    const int*   mask = (const int*)d_in[6];
    float* out = (float*)d_out;

    cudaFuncSetAttribute(qkv_kernel,
                         cudaFuncAttributeMaxDynamicSharedMemorySize, QKV_DYN_BYTES);
    cudaFuncSetAttribute(attn_kernel,
                         cudaFuncAttributeMaxDynamicSharedMemorySize, AT_DYN_BYTES);

    cvt_kernel<<<4096 + 1536, 256>>>(hs, w);
    bias_kernel<<<(H * N * N) / (256 * 4), 256>>>(rel, rel2);
    perm_kernel<<<B, 1024>>>(mask);
    msum_kernel<<<dim3(8, B, 4), 128>>>(hs, mask);

    dim3 g1(3 * HD / 128, (B * N) / 256);        // (24, 32)
    qkv_kernel<<<g1, 512, QKV_DYN_BYTES>>>(qb, vb);

    vgemm_kernel<<<1024, 256>>>(w, vb);

    dim3 g2(N / 128, H, B);                      // (8, 16, 8)
    attn_kernel<<<g2, 256, AT_DYN_BYTES>>>(out);
}

// round 17
// speedup vs baseline: 1.6812x; 1.0431x over previous
#include <cuda_runtime.h>
#include <cuda_fp16.h>
#include <math.h>
#include <stdint.h>

#define B 8
#define N 1024
#define H 16
#define D 64
#define HD 1024

// Scratch (allocation-free)
__device__ __half g_hsH[B * N * HD];       // fp16 copy of hidden_states
__device__ __half g_wH[3 * HD * HD];       // fp16 copy of qkv_w
__device__ __half g_Qh[B * H * N * D];     // original token order, *0.125
__device__ __half g_Kh[B * H * N * D];     // keys compacted (unmasked first)
__device__ __half g_Vh[B * H * N * D];     // [np][d] row-major, compacted
__device__ float  g_RB[H * N * N];         // combined bias, ORIGINAL key order
__device__ int    g_invp[B * N];           // permuted pos -> orig key
__device__ int    g_nun[B];                // # unmasked keys
__device__ float  g_msum8[8 * B * HD];     // 8 n-chunk partials of masked hs sum
__device__ float  g_Vsum[B * HD];          // sum of V over masked keys (fp32)

__device__ __forceinline__ uint32_t f2h2(float lo, float hi) {
    __half2 h = __floats2half2_rn(lo, hi);
    return *(uint32_t*)&h;
}

__device__ __forceinline__ void mma16(float* d, const uint32_t* a, const uint32_t* b) {
    asm volatile(
        "mma.sync.aligned.m16n8k16.row.col.f32.f16.f16.f32 "
        "{%0,%1,%2,%3}, {%4,%5,%6,%7}, {%8,%9}, {%0,%1,%2,%3};"
        : "+f"(d[0]), "+f"(d[1]), "+f"(d[2]), "+f"(d[3])
        : "r"(a[0]), "r"(a[1]), "r"(a[2]), "r"(a[3]), "r"(b[0]), "r"(b[1]));
}

__device__ __forceinline__ void ldm4(uint32_t* d, uint32_t a) {
    asm volatile("ldmatrix.sync.aligned.m8n8.x4.shared.b16 {%0,%1,%2,%3}, [%4];"
        : "=r"(d[0]), "=r"(d[1]), "=r"(d[2]), "=r"(d[3]) : "r"(a));
}

__device__ __forceinline__ void ldm2t(uint32_t* d, uint32_t a) {
    asm volatile("ldmatrix.sync.aligned.m8n8.x2.trans.shared.b16 {%0,%1}, [%2];"
        : "=r"(d[0]), "=r"(d[1]) : "r"(a));
}

#define STS128V(addr, u) asm volatile("st.shared.v4.b32 [%0], {%1,%2,%3,%4};" \
    :: "r"(addr), "r"((u).x), "r"((u).y), "r"((u).z), "r"((u).w) : "memory")
#define CP_ASYNC16(dst, src) asm volatile( \
    "cp.async.cg.shared.global [%0], [%1], 16;" :: "r"(dst), "l"(src) : "memory")
#define CP_COMMIT() asm volatile("cp.async.commit_group;" ::: "memory")
#define CP_WAIT0()  asm volatile("cp.async.wait_group 0;" ::: "memory")
#define CP_WAIT1()  asm volatile("cp.async.wait_group 1;" ::: "memory")

__device__ __forceinline__ uint32_t smem_u32(const void* p) {
    uint32_t a;
    asm("{ .reg .u64 t; cvta.to.shared.u64 t, %1; cvt.u32.u64 %0, t; }"
        : "=r"(a) : "l"(p));
    return a;
}

// ---------------------------------------------------------------------------
// Kernel 0: combined bias = rel_pos + rel_2d_pos
// ---------------------------------------------------------------------------
__global__ __launch_bounds__(256) void bias_kernel(
    const float* __restrict__ rel, const float* __restrict__ rel2)
{
    size_t i = ((size_t)blockIdx.x * 256 + threadIdx.x) * 4;
    float4 a = *(const float4*)&rel[i];
    float4 b = *(const float4*)&rel2[i];
    a.x += b.x; a.y += b.y; a.z += b.z; a.w += b.w;
    *(float4*)&g_RB[i] = a;
}

// ---------------------------------------------------------------------------
// Kernel C: fused fp32 -> fp16 conversion of hs (blocks < 4096) and W (rest)
// ---------------------------------------------------------------------------
__global__ __launch_bounds__(256) void cvt_kernel(
    const float* __restrict__ hs, const float* __restrict__ w)
{
    const int bx = blockIdx.x;
    const float* src;
    __half* dst;
    size_t i;
    if (bx < 4096) {
        i = ((size_t)bx * 256 + threadIdx.x) * 8;
        src = hs; dst = g_hsH;
    } else {
        i = ((size_t)(bx - 4096) * 256 + threadIdx.x) * 8;
        src = w; dst = g_wH;
    }
    float4 a = *(const float4*)&src[i];
    float4 b = *(const float4*)&src[i + 4];
    uint4 u;
    u.x = f2h2(a.x, a.y); u.y = f2h2(a.z, a.w);
    u.z = f2h2(b.x, b.y); u.w = f2h2(b.z, b.w);
    *(uint4*)&dst[i] = u;
}

// ---------------------------------------------------------------------------
// Kernel P: stable partition of keys per batch (unmasked first).
// ---------------------------------------------------------------------------
__global__ __launch_bounds__(1024) void perm_kernel(const int* __restrict__ mask)
{
    const int b = blockIdx.x, k = threadIdx.x;
    const int lane = k & 31, wid = k >> 5;
    const int u = (mask[b * N + k] == 0) ? 1 : 0;
    unsigned bal = __ballot_sync(0xffffffffu, u);
    int eU = __popc(bal & ((1u << lane) - 1));

    __shared__ int wsum[32];
    if (lane == 31) wsum[wid] = eU + u;
    __syncthreads();
    if (wid == 0) {
        int v = wsum[lane];
#pragma unroll
        for (int off = 1; off < 32; off <<= 1) {
            int t = __shfl_up_sync(0xffffffffu, v, off);
            if (lane >= off) v += t;
        }
        wsum[lane] = v;
    }
    __syncthreads();
    const int warp_off = (wid > 0) ? wsum[wid - 1] : 0;
    const int nun = wsum[31];
    const int scanU = warp_off + eU;
    const int pos = u ? scanU : (nun + (k - scanU));
    g_invp[b * N + pos] = k;
    if (k == 0) g_nun[b] = nun;
}

// ---------------------------------------------------------------------------
// Kernel M: 8-way n-split masked hs sums. Unconditional multiply-add
// (mf in {0,1}) so loads issue unpredicated -> full MLP. grid (4, B, 8).
// ---------------------------------------------------------------------------
__global__ __launch_bounds__(256) void msum_kernel(
    const float* __restrict__ hs, const int* __restrict__ mask)
{
    __shared__ float mf[128];
    const int b = blockIdx.y;
    const int z = blockIdx.z;
    const int n0 = z * 128;
    const int k = blockIdx.x * 256 + threadIdx.x;
    if (threadIdx.x < 128)
        mf[threadIdx.x] = (mask[b * N + n0 + threadIdx.x] != 0) ? 1.0f : 0.0f;
    __syncthreads();

    const float* p = hs + ((size_t)b * N + n0) * HD + k;
    float s0 = 0.0f, s1 = 0.0f;
#pragma unroll 4
    for (int n = 0; n < 128; n += 2) {
        s0 += p[(size_t)n * HD] * mf[n];
        s1 += p[(size_t)(n + 1) * HD] * mf[n + 1];
    }
    g_msum8[((size_t)z * B + b) * HD + k] = s0 + s1;
}

// ---------------------------------------------------------------------------
// Kernel G: Vsum[b][o] = (sum of 8 msum partials) . Wv[o] + nmask * vb[o]
// ---------------------------------------------------------------------------
__global__ __launch_bounds__(256) void vgemm_kernel(
    const float* __restrict__ w, const float* __restrict__ vb)
{
    const int lane = threadIdx.x & 31;
    const int idx = blockIdx.x * 8 + (threadIdx.x >> 5);
    const int b = idx >> 10, o = idx & 1023;
    const float* wr = w + (size_t)(2048 + o) * HD;
    float s = 0.0f;
#pragma unroll
    for (int it = 0; it < 8; it++) {
        int k4 = it * 32 + lane;
        float4 wv = ((const float4*)wr)[k4];
        float4 mv = make_float4(0.f, 0.f, 0.f, 0.f);
#pragma unroll
        for (int pp = 0; pp < 8; pp++) {
            const float4* mp = (const float4*)(g_msum8 + ((size_t)pp * B + b) * HD);
            float4 t = mp[k4];
            mv.x += t.x; mv.y += t.y; mv.z += t.z; mv.w += t.w;
        }
        s += wv.x * mv.x + wv.y * mv.y + wv.z * mv.z + wv.w * mv.w;
    }
#pragma unroll
    for (int off = 16; off > 0; off >>= 1)
        s += __shfl_xor_sync(0xffffffffu, s, off);
    if (lane == 0) {
        float nm = (float)(N - g_nun[b]);
        g_Vsum[b * HD + o] = s + nm * vb[o];
    }
}

// ---------------------------------------------------------------------------
// Kernel 1: QKV projection, fp16 inputs, cp.async 3-stage pipeline, BK=32,
// ldmatrix fragment loads. 512 threads, tile 128(o) x 256(tok).
// ---------------------------------------------------------------------------
#define QP 20
#define QA_W (128 * QP)
#define QB_W (256 * QP)
#define QS_W (QA_W + QB_W)
#define QKV_DYN_BYTES (3 * QS_W * 4)

__global__ __launch_bounds__(512) void qkv_kernel(
    const float* __restrict__ qb, const float* __restrict__ vb)
{
    extern __shared__ uint32_t sm[];
    __shared__ int invp_s[256];
    const uint32_t smA = smem_u32(sm);

    const int tid  = threadIdx.x;
    const int lane = tid & 31;
    const int warp = tid >> 5;
    const int wo = (warp >> 2) * 32;
    const int wt = (warp & 3) * 64;
    const int o0 = blockIdx.x * 128;
    const int t0 = blockIdx.y * 256;
    const int r = lane >> 2;
    const int c = lane & 3;
    const int b0 = t0 >> 10;
    const int t0l = t0 & 1023;
    const int seg = o0 >> 10;
    const int am = ((lane >> 3) & 1) * 8 + (lane & 7);
    const int ac = (lane >> 4) * 4;

    if (seg != 0) {
        const int ntt = (g_nun[b0] + 255) >> 8;
        if ((t0l >> 8) >= ntt) return;
    }

    if (tid < 256) invp_s[tid] = g_invp[b0 * N + t0l + tid];
    __syncthreads();

    float acc[2][8][4];
#pragma unroll
    for (int g = 0; g < 2; g++)
#pragma unroll
        for (int nj = 0; nj < 8; nj++)
#pragma unroll
            for (int q = 0; q < 4; q++) acc[g][nj][q] = 0.0f;

    auto load_stage = [&](int kc, int buf) {
        const int k0 = kc * 32;
        const uint32_t base = smA + buf * QS_W * 4;
        {
            int row = tid >> 2, f = tid & 3;
            CP_ASYNC16(base + (row * QP + 4 * f) * 4,
                       g_wH + (size_t)(o0 + row) * HD + k0 + 8 * f);
        }
#pragma unroll
        for (int i = 0; i < 2; i++) {
            int slot = tid + 512 * i;
            int row = slot >> 2, f = slot & 3;
            int grow = seg ? (b0 * N + invp_s[row]) : (t0 + row);
            CP_ASYNC16(base + (QA_W + row * QP + 4 * f) * 4,
                       g_hsH + (size_t)grow * HD + k0 + 8 * f);
        }
    };

    load_stage(0, 0); CP_COMMIT();
    load_stage(1, 1); CP_COMMIT();

    for (int kc = 0; kc < 32; kc++) {
        const int buf = kc - (kc / 3) * 3;
        CP_WAIT1();
        __syncthreads();

        if (kc + 2 < 32) load_stage(kc + 2, (kc + 2) - ((kc + 2) / 3) * 3);
        CP_COMMIT();

        const uint32_t Aa = smA + (buf * QS_W) * 4;
        const uint32_t Ba = Aa + QA_W * 4;
#pragma unroll
        for (int ks = 0; ks < 2; ks++) {
            const int kb = ks * 8;
            uint32_t a[2][4], bb[8][2];
#pragma unroll
            for (int g = 0; g < 2; g++)
                ldm4(a[g], Aa + ((wo + 16 * g + am) * QP + kb + ac) * 4);
#pragma unroll
            for (int j = 0; j < 4; j++) {
                uint32_t t4[4];
                ldm4(t4, Ba + ((wt + 16 * j + am) * QP + kb + ac) * 4);
                bb[2 * j][0] = t4[0];     bb[2 * j][1] = t4[2];
                bb[2 * j + 1][0] = t4[1]; bb[2 * j + 1][1] = t4[3];
            }
#pragma unroll
            for (int g = 0; g < 2; g++)
#pragma unroll
                for (int nj = 0; nj < 8; nj++)
                    mma16(acc[g][nj], a[g], bb[nj]);
        }
    }

    // epilogue: contiguous token-row writes
#pragma unroll
    for (int g = 0; g < 2; g++) {
#pragma unroll
        for (int rr = 0; rr < 2; rr++) {
            int o = o0 + wo + 16 * g + r + 8 * rr;
            int hd = o & 1023, h = hd >> 6, d = hd & 63;
            float addb = (seg == 0) ? qb[hd] : ((seg == 2) ? vb[hd] : 0.0f);
#pragma unroll
            for (int nj = 0; nj < 8; nj++) {
                int tokl = wt + 8 * nj + 2 * c;
                int n = t0l + tokl;
                float v0 = acc[g][nj][2 * rr + 0];
                float v1 = acc[g][nj][2 * rr + 1];
                size_t idx = (((size_t)(b0 * H + h)) * N + n) * D + d;
                if (seg == 0) {
                    g_Qh[idx]     = __float2half((v0 + addb) * 0.125f);
                    g_Qh[idx + D] = __float2half((v1 + addb) * 0.125f);
                } else if (seg == 1) {
                    g_Kh[idx]     = __float2half(v0);
                    g_Kh[idx + D] = __float2half(v1);
                } else {
                    g_Vh[idx]     = __float2half(v0 + addb);
                    g_Vh[idx + D] = __float2half(v1 + addb);
                }
            }
        }
    }
}

// ---------------------------------------------------------------------------
// Kernel 2: flash attention (round-12/16 version). 2 CTAs/SM.
// ---------------------------------------------------------------------------
#define AT_PITCH 36
#define AT_KW (64 * AT_PITCH)
#define AT_PSW (128 * AT_PITCH)
#define AT_DYN_BYTES ((4 * AT_KW + AT_PSW + N) * 4)

__global__ __launch_bounds__(256, 2) void attn_kernel(float* __restrict__ out)
{
    extern __shared__ uint32_t dynsm[];
    uint32_t* Ps = dynsm + 4 * AT_KW;
    int* invp_s = (int*)(dynsm + 4 * AT_KW + AT_PSW);
    const uint32_t dynA = smem_u32(dynsm);
    const uint32_t PsA  = dynA + 4 * AT_KW * 4;

    const int tid  = threadIdx.x;
    const int lane = tid & 31;
    const int warp = tid >> 5;
    const int q0 = blockIdx.x * 128;
    const int h  = blockIdx.y;
    const int b  = blockIdx.z;
    const int qw = warp * 16;
    const int r = lane >> 2;
    const int c = lane & 3;

    const __half* Qh = g_Qh + (size_t)(b * H + h) * N * D;
    const __half* Kh = g_Kh + (size_t)(b * H + h) * N * D;
    const __half* Vh = g_Vh + (size_t)(b * H + h) * N * D;
    const float*  rb = g_RB + (size_t)h * N * N;

    const int nun = g_nun[b];
    const int ntiles = (nun + 63) >> 6;

    for (int i = tid; i < N; i += 256) invp_s[i] = g_invp[b * N + i];

#pragma unroll
    for (int i = 0; i < 4; i++) {
        int slot = lane + 32 * i;
        int row16 = slot >> 3, j = slot & 7;
        uint4 v = ((const uint4*)(Qh + (size_t)(q0 + qw + row16) * D))[j];
        STS128V(PsA + ((qw + row16) * AT_PITCH + 4 * j) * 4, v);
    }
    __syncwarp();

    uint32_t qa[4][4];
#pragma unroll
    for (int ks = 0; ks < 4; ks++) {
        qa[ks][0] = Ps[(qw + r) * AT_PITCH + 8 * ks + c];
        qa[ks][1] = Ps[(qw + r + 8) * AT_PITCH + 8 * ks + c];
        qa[ks][2] = Ps[(qw + r) * AT_PITCH + 8 * ks + c + 4];
        qa[ks][3] = Ps[(qw + r + 8) * AT_PITCH + 8 * ks + c + 4];
    }

    auto load_tile = [&](int t, int buf) {
        const int k0 = t * 64;
        const uint32_t kb = dynA + (buf * AT_KW) * 4;
        const uint32_t vbuf = dynA + ((2 + buf) * AT_KW) * 4;
#pragma unroll
        for (int i = 0; i < 2; i++) {
            int slot = tid + 256 * i;
            int row = slot >> 3, j = slot & 7;
            CP_ASYNC16(kb + (row * AT_PITCH + 4 * j) * 4,
                       Kh + (size_t)(k0 + row) * D + 8 * j);
            CP_ASYNC16(vbuf + (row * AT_PITCH + 4 * j) * 4,
                       Vh + (size_t)(k0 + row) * D + 8 * j);
        }
    };

    float m0v = -INFINITY, m1v = -INFINITY, l0 = 0.0f, l1 = 0.0f;
    float oacc[8][4];
#pragma unroll
    for (int nb = 0; nb < 8; nb++)
#pragma unroll
        for (int q = 0; q < 4; q++) oacc[nb][q] = 0.0f;

    load_tile(0, 0);
    CP_COMMIT();

    for (int t = 0; t < ntiles; t++) {
        const int buf = t & 1;
        const int k0 = t * 64;
        CP_WAIT0();
        __syncthreads();

        if (t + 1 < ntiles) {
            load_tile(t + 1, buf ^ 1);
            CP_COMMIT();
        }

        const uint32_t* Ks = dynsm + buf * AT_KW;
        const uint32_t vldm = dynA + ((2 + buf) * AT_KW + (lane & 15) * AT_PITCH) * 4;

        float sacc[8][4];
#pragma unroll
        for (int nb = 0; nb < 8; nb++)
#pragma unroll
            for (int q = 0; q < 4; q++) sacc[nb][q] = 0.0f;

#pragma unroll
        for (int ks = 0; ks < 4; ks++) {
            uint32_t bbk[8][2];
#pragma unroll
            for (int nb = 0; nb < 8; nb++) {
                bbk[nb][0] = Ks[(8 * nb + r) * AT_PITCH + 8 * ks + c];
                bbk[nb][1] = Ks[(8 * nb + r) * AT_PITCH + 8 * ks + c + 4];
            }
#pragma unroll
            for (int nb = 0; nb < 8; nb++) mma16(sacc[nb], qa[ks], bbk[nb]);
        }

        const int row0 = q0 + qw + r;
        float rmax0 = -INFINITY, rmax1 = -INFINITY;
#pragma unroll
        for (int nb = 0; nb < 8; nb++) {
            int p0 = k0 + 8 * nb + 2 * c;
            int c0 = invp_s[p0], c1 = invp_s[p0 + 1];
            float s0 = sacc[nb][0] + rb[(size_t)row0 * N + c0];
            float s1 = sacc[nb][1] + rb[(size_t)row0 * N + c1];
            float s2 = sacc[nb][2] + rb[(size_t)(row0 + 8) * N + c0];
            float s3 = sacc[nb][3] + rb[(size_t)(row0 + 8) * N + c1];
            if (p0 >= nun)     { s0 = -1e30f; s2 = -1e30f; }
            if (p0 + 1 >= nun) { s1 = -1e30f; s3 = -1e30f; }
            sacc[nb][0] = s0; sacc[nb][1] = s1; sacc[nb][2] = s2; sacc[nb][3] = s3;
            rmax0 = fmaxf(rmax0, fmaxf(s0, s1));
            rmax1 = fmaxf(rmax1, fmaxf(s2, s3));
        }
        rmax0 = fmaxf(rmax0, __shfl_xor_sync(0xffffffffu, rmax0, 1));
        rmax0 = fmaxf(rmax0, __shfl_xor_sync(0xffffffffu, rmax0, 2));
        rmax1 = fmaxf(rmax1, __shfl_xor_sync(0xffffffffu, rmax1, 1));
        rmax1 = fmaxf(rmax1, __shfl_xor_sync(0xffffffffu, rmax1, 2));

        float mn0 = fmaxf(m0v, rmax0), mn1 = fmaxf(m1v, rmax1);
        float sc0 = __expf(m0v - mn0), sc1 = __expf(m1v - mn1);
        m0v = mn0; m1v = mn1;

        float rs0 = 0.0f, rs1 = 0.0f;
#pragma unroll
        for (int nb = 0; nb < 8; nb++) {
            float p0 = __expf(sacc[nb][0] - mn0);
            float p1 = __expf(sacc[nb][1] - mn0);
            float p2 = __expf(sacc[nb][2] - mn1);
            float p3 = __expf(sacc[nb][3] - mn1);
            rs0 += p0 + p1;
            rs1 += p2 + p3;
            Ps[(qw + r) * AT_PITCH + 4 * nb + c]     = f2h2(p0, p1);
            Ps[(qw + r + 8) * AT_PITCH + 4 * nb + c] = f2h2(p2, p3);
        }
        rs0 += __shfl_xor_sync(0xffffffffu, rs0, 1);
        rs0 += __shfl_xor_sync(0xffffffffu, rs0, 2);
        rs1 += __shfl_xor_sync(0xffffffffu, rs1, 1);
        rs1 += __shfl_xor_sync(0xffffffffu, rs1, 2);
        l0 = l0 * sc0 + rs0;
        l1 = l1 * sc1 + rs1;
#pragma unroll
        for (int nb = 0; nb < 8; nb++) {
            oacc[nb][0] *= sc0; oacc[nb][1] *= sc0;
            oacc[nb][2] *= sc1; oacc[nb][3] *= sc1;
        }
        __syncwarp();

#pragma unroll
        for (int ks = 0; ks < 4; ks++) {
            uint32_t pa[4];
            pa[0] = Ps[(qw + r) * AT_PITCH + 8 * ks + c];
            pa[1] = Ps[(qw + r + 8) * AT_PITCH + 8 * ks + c];
            pa[2] = Ps[(qw + r) * AT_PITCH + 8 * ks + c + 4];
            pa[3] = Ps[(qw + r + 8) * AT_PITCH + 8 * ks + c + 4];
            const uint32_t vbase = vldm + (16 * ks * AT_PITCH) * 4;
#pragma unroll
            for (int nb = 0; nb < 8; nb++) {
                uint32_t bbv[2];
                ldm2t(bbv, vbase + nb * 16);
                mma16(oacc[nb], pa, bbv);
            }
        }
    }

    const int nmask = N - nun;
    float cM0 = 0.0f, cM1 = 0.0f;
    if (nmask > 0) {
        float mf0 = fmaxf(m0v, 1e-8f), mf1 = fmaxf(m1v, 1e-8f);
        float sc0 = __expf(m0v - mf0), sc1 = __expf(m1v - mf1);
        float pm0 = __expf(1e-8f - mf0), pm1 = __expf(1e-8f - mf1);
        l0 = l0 * sc0 + (float)nmask * pm0;
        l1 = l1 * sc1 + (float)nmask * pm1;
        cM0 = pm0; cM1 = pm1;
#pragma unroll
        for (int nb = 0; nb < 8; nb++) {
            oacc[nb][0] *= sc0; oacc[nb][1] *= sc0;
            oacc[nb][2] *= sc1; oacc[nb][3] *= sc1;
        }
    }

    const float* vs = g_Vsum + b * HD + h * D;
    const float inv0 = 1.0f / l0, inv1 = 1.0f / l1;
    const int n0_ = q0 + qw + r;
#pragma unroll
    for (int nb = 0; nb < 8; nb++) {
        int d = 8 * nb + 2 * c;
        float2 vv = *(const float2*)&vs[d];
        float2 v0; v0.x = (oacc[nb][0] + cM0 * vv.x) * inv0;
        v0.y = (oacc[nb][1] + cM0 * vv.y) * inv0;
        *(float2*)&out[((size_t)b * N + n0_) * HD + h * D + d] = v0;
        float2 v1; v1.x = (oacc[nb][2] + cM1 * vv.x) * inv1;
        v1.y = (oacc[nb][3] + cM1 * vv.y) * inv1;
        *(float2*)&out[((size_t)b * N + n0_ + 8) * HD + h * D + d] = v1;
    }
}

extern "C" void kernel_launch(void* const* d_in, const int* in_sizes, int n_in,
                              void* d_out, int out_size)
{
    (void)in_sizes; (void)n_in; (void)out_size;
    const float* hs   = (const float*)d_in[0];
    const float* w    = (const float*)d_in[1];
    const float* qb   = (const float*)d_in[2];
    const float* vb   = (const float*)d_in[3];
    const float* rel  = (const float*)d_in[4];
    const float* rel2 = (const float*)d_in[5];
    const int*   mask = (const int*)d_in[6];
    float* out = (float*)d_out;

    cudaFuncSetAttribute(qkv_kernel,
                         cudaFuncAttributeMaxDynamicSharedMemorySize, QKV_DYN_BYTES);
    cudaFuncSetAttribute(attn_kernel,
                         cudaFuncAttributeMaxDynamicSharedMemorySize, AT_DYN_BYTES);

    cvt_kernel<<<4096 + 1536, 256>>>(hs, w);
    bias_kernel<<<(H * N * N) / (256 * 4), 256>>>(rel, rel2);
    perm_kernel<<<B, 1024>>>(mask);
    msum_kernel<<<dim3(4, B, 8), 256>>>(hs, mask);

    dim3 g1(3 * HD / 128, (B * N) / 256);        // (24, 32)
    qkv_kernel<<<g1, 512, QKV_DYN_BYTES>>>(qb, vb);

    vgemm_kernel<<<1024, 256>>>(w, vb);

    dim3 g2(N / 128, H, B);                      // (8, 16, 8)
    attn_kernel<<<g2, 256, AT_DYN_BYTES>>>(out);
}